// round 15
// baseline (speedup 1.0000x reference)
#include <cuda_runtime.h>
#include <cuda_bf16.h>
#include <cuda_fp16.h>
#include <math.h>
#include <stdint.h>

#define BB 4
#define SS 128
#define DD 512
#define HH 8
#define DH 64
#define FF 2048
#define RR 8
#define BS (BB*SS)          // 512
#define UU 262144           // 512*512
#define THRESH 0.1f
#define MAXE 8192

typedef __nv_bfloat16 bf16;

// ======================= helpers =======================
__device__ __forceinline__ uint32_t smem_u32(const void* p){
    uint32_t a;
    asm("{ .reg .u64 t; cvta.to.shared.u64 t, %1; cvt.u32.u64 %0, t; }" : "=r"(a) : "l"(p));
    return a;
}
__device__ __forceinline__ void ldsm4(uint32_t& r0, uint32_t& r1, uint32_t& r2, uint32_t& r3,
                                      uint32_t addr){
    asm volatile("ldmatrix.sync.aligned.m8n8.x4.shared.b16 {%0,%1,%2,%3}, [%4];"
                 : "=r"(r0), "=r"(r1), "=r"(r2), "=r"(r3) : "r"(addr));
}
__device__ __forceinline__ void mma16816(float* d, const uint32_t* a, const uint32_t* b){
    asm volatile("mma.sync.aligned.m16n8k16.row.col.f32.bf16.bf16.f32 "
                 "{%0,%1,%2,%3}, {%4,%5,%6,%7}, {%8,%9}, {%0,%1,%2,%3};"
                 : "+f"(d[0]), "+f"(d[1]), "+f"(d[2]), "+f"(d[3])
                 : "r"(a[0]), "r"(a[1]), "r"(a[2]), "r"(a[3]), "r"(b[0]), "r"(b[1]));
}
__device__ __forceinline__ void mma16816h(float* d, const uint32_t* a, const uint32_t* b){
    asm volatile("mma.sync.aligned.m16n8k16.row.col.f32.f16.f16.f32 "
                 "{%0,%1,%2,%3}, {%4,%5,%6,%7}, {%8,%9}, {%0,%1,%2,%3};"
                 : "+f"(d[0]), "+f"(d[1]), "+f"(d[2]), "+f"(d[3])
                 : "r"(a[0]), "r"(a[1]), "r"(a[2]), "r"(a[3]), "r"(b[0]), "r"(b[1]));
}
__device__ __forceinline__ void cpa16(uint32_t s, const void* g){
    asm volatile("cp.async.cg.shared.global [%0], [%1], 16;" :: "r"(s), "l"(g));
}
__device__ __forceinline__ void cpa_commit(){
    asm volatile("cp.async.commit_group;" ::: "memory");
}
template<int N> __device__ __forceinline__ void cpa_wait(){
    asm volatile("cp.async.wait_group %0;" :: "n"(N) : "memory");
}

// ======================= scratch (device globals) =======================
__device__ bf16  g_wTh[14*UU];          // bf16 hi weights (units 0..13)
__device__ bf16  g_wTl[14*UU];          // bf16 lo weights
__device__ __half g_wT16[9*UU];         // fp16 weights: kg relations 0..7, s2n (unit 8)
__device__ float g_b3[3*DD];            // packed q/k/v biases
__device__ bf16  g_xnh[UU], g_xnl[UU];
__device__ float g_qkv[3*UU];
__device__ float g_attn[BB*HH*SS*SS];
__device__ bf16  g_ctxh[UU], g_ctxl[UU];
__device__ bf16  g_aoh[UU],  g_aol[UU];
__device__ bf16  g_hidh[BS*FF], g_hidl[BS*FF];
__device__ float g_nupart[4*UU];        // split-K partials for nu
__device__ float g_nu[UU];
__device__ bf16  g_nuh[UU], g_nul[UU];
__device__ __half g_nu16[UU];
__device__ float g_ab[2*UU];            // a/b parts
__device__ float g_trans[8*UU];         // RGCN transform slabs [r][n][d], r=1..7 used
__device__ int   g_rel[BB*SS*SS];
__device__ __half g_rs16[UU];           // reasoned, fp16
__device__ float g_nr[UU];
__device__ int2  g_elist[MAXE];
__device__ int   g_ecnt;

// ========== prep: fused weight transpose/convert + ln1 + bias pack + counter reset ==========
#define WBLK 5888

__global__ void prep_k(const float* __restrict__ wq, const float* __restrict__ wk,
                       const float* __restrict__ wv, const float* __restrict__ wo,
                       const float* __restrict__ w1, const float* __restrict__ w2,
                       const float* __restrict__ rc, const float* __restrict__ kg,
                       const float* __restrict__ s2n,
                       const float* __restrict__ bq, const float* __restrict__ bk,
                       const float* __restrict__ bvv,
                       const float* __restrict__ x, const float* __restrict__ g,
                       const float* __restrict__ b,
                       bf16* __restrict__ oh, bf16* __restrict__ ol)
{
    __shared__ float tile[32][33];
    __shared__ float rbuf[256];
    int bid = blockIdx.x, t = threadIdx.x;

    if (bid < WBLK) {
        int z = bid >> 8, rem = bid & 255;
        int bx = rem & 15, by = rem >> 4;
        const float* src; int ld; long dst; int dld;
        if (z < 3)       { const float* q3[3] = {wq, wk, wv};
                           src = q3[z]; ld = DD; dst = (long)z*UU; dld = DD; }
        else if (z == 3) { src = wo; ld = DD; dst = 3L*UU; dld = DD; }
        else if (z < 8)  { int u = z-4; src = w1 + u*DD; ld = FF; dst = 4L*UU + (long)u*UU; dld = DD; }
        else if (z < 12) { int u = z-8; src = w2 + (long)u*UU; ld = DD; dst = 8L*UU + (long)u*DD; dld = FF; }
        else if (z < 14) { int u = z-12; src = rc + (long)u*UU; ld = DD; dst = (12L+u)*UU; dld = DD; }
        else if (z < 22) { int u = z-14; src = kg + (long)u*UU; ld = DD; dst = (long)u*UU; dld = DD; }
        else             { src = s2n; ld = DD; dst = 8L*UU; dld = DD; }

        int k0 = by * 32, n0 = bx * 32;
        int tx = t & 31, ty = t >> 5;          // (32, 8)
#pragma unroll
        for (int i = 0; i < 4; i++)
            tile[ty + 8*i][tx] = __ldg(src + (long)(k0 + ty + 8*i) * ld + n0 + tx);
        __syncthreads();
        bool f16 = z >= 14;
#pragma unroll
        for (int i = 0; i < 2; i++) {
            int p = t + i * 256;
            int n = p >> 4, kp = p & 15;
            float v0 = tile[2*kp    ][n];
            float v1 = tile[2*kp + 1][n];
            long off = dst + (long)(n0 + n) * dld + k0 + 2*kp;
            if (f16) {
                __half2 ph; ph.x = __float2half(v0); ph.y = __float2half(v1);
                *(__half2*)&g_wT16[off] = ph;
            } else {
                bf16 h0 = __float2bfloat16(v0), h1 = __float2bfloat16(v1);
                __nv_bfloat162 ph; ph.x = h0; ph.y = h1;
                __nv_bfloat162 pl;
                pl.x = __float2bfloat16(v0 - __bfloat162float(h0));
                pl.y = __float2bfloat16(v1 - __bfloat162float(h1));
                *(__nv_bfloat162*)&g_wTh[off] = ph;
                *(__nv_bfloat162*)&g_wTl[off] = pl;
            }
        }
        return;
    }

    int row = bid - WBLK;                      // 0..511, ln1
    if (row == 0) {
        for (int i = t; i < DD; i += 256) {
            g_b3[i] = bq[i]; g_b3[DD+i] = bk[i]; g_b3[2*DD+i] = bvv[i];
        }
        if (t == 0) g_ecnt = 0;
    }
    long base = (long)row * DD;
    float v0 = x[base + t], v1 = x[base + t + 256];
    rbuf[t] = v0 + v1; __syncthreads();
    for (int s = 128; s > 0; s >>= 1) { if (t < s) rbuf[t] += rbuf[t + s]; __syncthreads(); }
    float mean = rbuf[0] * (1.0f / 512.0f);
    __syncthreads();
    float d0 = v0 - mean, d1 = v1 - mean;
    rbuf[t] = d0 * d0 + d1 * d1; __syncthreads();
    for (int s = 128; s > 0; s >>= 1) { if (t < s) rbuf[t] += rbuf[t + s]; __syncthreads(); }
    float rs = rsqrtf(rbuf[0] * (1.0f / 512.0f) + 1e-5f);
    float o0 = d0 * rs * g[t] + b[t];
    float o1 = d1 * rs * g[t + 256] + b[t + 256];
    bf16 h0 = __float2bfloat16(o0), h1 = __float2bfloat16(o1);
    oh[base + t] = h0;       ol[base + t]       = __float2bfloat16(o0 - __bfloat162float(h0));
    oh[base + t + 256] = h1; ol[base + t + 256] = __float2bfloat16(o1 - __bfloat162float(h1));
}

// ======================= mma.sync bf16 3-pass GEMM (64x64 tile, 2-stage) =======================
#define FL_F32  1
#define FL_HILO 2
#define FL_RELU 4

#define TSTRIDE 144
#define TILE_B  9216
#define STAGE_B 36864
#define GSM     73728

__global__ void __launch_bounds__(256, 3)
gemm_mma(const bf16* __restrict__ Ah, const bf16* __restrict__ Al, int lda, long a_z,
         const bf16* __restrict__ Bh, const bf16* __restrict__ Bl, long b_z, int ldb,
         const float* __restrict__ bias, int bias_z,
         float* __restrict__ C, long c_z, int ldc,
         bf16* __restrict__ Ch, bf16* __restrict__ Cl, int ldch,
         int K, int flags)
{
    extern __shared__ char sm[];
    uint32_t sb = smem_u32(sm);
    const int tid = threadIdx.x, lane = tid & 31, wid = tid >> 5;
    const int wm = wid >> 2, wn = wid & 3;
    const int m0 = blockIdx.y * 64, n0 = blockIdx.x * 64, z = blockIdx.z;
    const bf16* Ahp = Ah + (long)z * a_z;
    const bf16* Alp = Al + (long)z * a_z;
    const bf16* Bhp = Bh + (long)z * b_z;
    const bf16* Blp = Bl + (long)z * b_z;

    const int ld_r = tid >> 3, ld_c = (tid & 7) * 8;
    const uint32_t s_wr = (uint32_t)(ld_r * TSTRIDE + ld_c * 2);

    const int a_r = (lane & 7) + ((lane >> 3) & 1) * 8;
    const int a_c8 = (lane >> 4) * 8;
    const uint32_t aoff = (uint32_t)((wm * 32 + a_r) * TSTRIDE + a_c8 * 2);
    const int b_r = (lane & 7) + (lane >> 4) * 8;
    const int b_c8 = ((lane >> 3) & 1) * 8;
    const uint32_t boff = (uint32_t)((wn * 16 + b_r) * TSTRIDE + b_c8 * 2);

    float acc[2][2][4];
#pragma unroll
    for (int i = 0; i < 2; i++)
#pragma unroll
        for (int j = 0; j < 2; j++)
#pragma unroll
            for (int q = 0; q < 4; q++) acc[i][j][q] = 0.f;

    uint32_t fah[2][2][4], fal[2][2][4], fbh[2][2][2], fbl[2][2][2];

    const int nch = K >> 6;

    auto issue = [&](int kk, int st){
        uint32_t base = sb + st * STAGE_B + s_wr;
        const bf16* ga0 = Ahp + (long)(m0 + ld_r) * lda + kk + ld_c;
        const bf16* ga1 = Alp + (long)(m0 + ld_r) * lda + kk + ld_c;
        const bf16* gb0 = Bhp + (long)(n0 + ld_r) * ldb + kk + ld_c;
        const bf16* gb1 = Blp + (long)(n0 + ld_r) * ldb + kk + ld_c;
        cpa16(base,                         ga0);
        cpa16(base + 32 * TSTRIDE,          ga0 + 32 * lda);
        cpa16(base + TILE_B,                ga1);
        cpa16(base + TILE_B + 32 * TSTRIDE, ga1 + 32 * lda);
        cpa16(base + 2 * TILE_B,                gb0);
        cpa16(base + 2 * TILE_B + 32 * TSTRIDE, gb0 + 32 * ldb);
        cpa16(base + 3 * TILE_B,                gb1);
        cpa16(base + 3 * TILE_B + 32 * TSTRIDE, gb1 + 32 * ldb);
        cpa_commit();
    };

    issue(0, 0);
    for (int i = 0; i < nch; i++) {
        if (i + 1 < nch) { issue((i + 1) << 6, (i + 1) & 1); cpa_wait<1>(); }
        else             { cpa_wait<0>(); }
        __syncthreads();

        uint32_t st = sb + (i & 1) * STAGE_B;

        {
            ldsm4(fbh[0][0][0], fbh[0][0][1], fbh[0][1][0], fbh[0][1][1], st + 2*TILE_B + boff);
            ldsm4(fbl[0][0][0], fbl[0][0][1], fbl[0][1][0], fbl[0][1][1], st + 3*TILE_B + boff);
#pragma unroll
            for (int mf = 0; mf < 2; mf++)
                ldsm4(fah[0][mf][0], fah[0][mf][1], fah[0][mf][2], fah[0][mf][3],
                      st + aoff + mf * (16*TSTRIDE));
#pragma unroll
            for (int mf = 0; mf < 2; mf++)
                ldsm4(fal[0][mf][0], fal[0][mf][1], fal[0][mf][2], fal[0][mf][3],
                      st + TILE_B + aoff + mf * (16*TSTRIDE));
        }

#pragma unroll
        for (int ks = 0; ks < 4; ks++) {
            const int cur = ks & 1, nxt = cur ^ 1;
            if (ks < 3) {
                uint32_t kb = (ks + 1) * 32;
                ldsm4(fbh[nxt][0][0], fbh[nxt][0][1], fbh[nxt][1][0], fbh[nxt][1][1],
                      st + 2*TILE_B + boff + kb);
                ldsm4(fbl[nxt][0][0], fbl[nxt][0][1], fbl[nxt][1][0], fbl[nxt][1][1],
                      st + 3*TILE_B + boff + kb);
#pragma unroll
                for (int mf = 0; mf < 2; mf++)
                    ldsm4(fah[nxt][mf][0], fah[nxt][mf][1], fah[nxt][mf][2], fah[nxt][mf][3],
                          st + aoff + mf * (16*TSTRIDE) + kb);
#pragma unroll
                for (int mf = 0; mf < 2; mf++)
                    ldsm4(fal[nxt][mf][0], fal[nxt][mf][1], fal[nxt][mf][2], fal[nxt][mf][3],
                          st + TILE_B + aoff + mf * (16*TSTRIDE) + kb);
            }
#pragma unroll
            for (int mf = 0; mf < 2; mf++)
#pragma unroll
                for (int nf = 0; nf < 2; nf++) mma16816(acc[mf][nf], fah[cur][mf], fbh[cur][nf]);
#pragma unroll
            for (int mf = 0; mf < 2; mf++)
#pragma unroll
                for (int nf = 0; nf < 2; nf++) mma16816(acc[mf][nf], fah[cur][mf], fbl[cur][nf]);
#pragma unroll
            for (int mf = 0; mf < 2; mf++)
#pragma unroll
                for (int nf = 0; nf < 2; nf++) mma16816(acc[mf][nf], fal[cur][mf], fbh[cur][nf]);
        }
        __syncthreads();
    }

    const int g = lane >> 2, tg = lane & 3;
    const float* bp = bias ? bias + (long)z * bias_z : nullptr;
    float* Cz = C ? C + (long)z * c_z : nullptr;
#pragma unroll
    for (int mf = 0; mf < 2; mf++) {
#pragma unroll
        for (int nf = 0; nf < 2; nf++) {
            int row = m0 + wm * 32 + mf * 16 + g;
            int col = n0 + wn * 16 + nf * 8 + tg * 2;
            float v0 = acc[mf][nf][0], v1 = acc[mf][nf][1];
            float v2 = acc[mf][nf][2], v3 = acc[mf][nf][3];
            if (bp) {
                float bb0 = __ldg(bp + col), bb1 = __ldg(bp + col + 1);
                v0 += bb0; v1 += bb1; v2 += bb0; v3 += bb1;
            }
            if (flags & FL_RELU) {
                v0 = fmaxf(v0, 0.f); v1 = fmaxf(v1, 0.f);
                v2 = fmaxf(v2, 0.f); v3 = fmaxf(v3, 0.f);
            }
            if (flags & FL_F32) {
                *(float2*)&Cz[(long)row * ldc + col] = make_float2(v0, v1);
                *(float2*)&Cz[(long)(row + 8) * ldc + col] = make_float2(v2, v3);
            }
            if (flags & FL_HILO) {
                bf16 h0 = __float2bfloat16(v0), h1 = __float2bfloat16(v1);
                bf16 h2 = __float2bfloat16(v2), h3 = __float2bfloat16(v3);
                __nv_bfloat162 ph0; ph0.x = h0; ph0.y = h1;
                __nv_bfloat162 ph1; ph1.x = h2; ph1.y = h3;
                __nv_bfloat162 pl0, pl1;
                pl0.x = __float2bfloat16(v0 - __bfloat162float(h0));
                pl0.y = __float2bfloat16(v1 - __bfloat162float(h1));
                pl1.x = __float2bfloat16(v2 - __bfloat162float(h2));
                pl1.y = __float2bfloat16(v3 - __bfloat162float(h3));
                *(__nv_bfloat162*)&Ch[(long)row * ldch + col] = ph0;
                *(__nv_bfloat162*)&Cl[(long)row * ldch + col] = pl0;
                *(__nv_bfloat162*)&Ch[(long)(row + 8) * ldch + col] = ph1;
                *(__nv_bfloat162*)&Cl[(long)(row + 8) * ldch + col] = pl1;
            }
        }
    }
}

// ============ small-tile bf16 variant: 32x64 CTA tile ============
#define OA_H2 0
#define OA_L2 4608
#define OB_H2 9216
#define OB_L2 18432
#define STAGE2 27648
#define GSM2 55296

__global__ void __launch_bounds__(256, 4)
gemm_sm(const bf16* __restrict__ Ah, const bf16* __restrict__ Al, int lda, long a_z,
        const bf16* __restrict__ Bh, const bf16* __restrict__ Bl, long b_z, int ldb,
        const float* __restrict__ bias, int bias_z,
        float* __restrict__ C, long c_z, int ldc,
        bf16* __restrict__ Ch, bf16* __restrict__ Cl, int ldch,
        int K, int flags)
{
    extern __shared__ char sm[];
    uint32_t sb = smem_u32(sm);
    const int tid = threadIdx.x, lane = tid & 31, wid = tid >> 5;
    const int wm = wid >> 2, wn = wid & 3;
    const int m0 = blockIdx.y * 32, n0 = blockIdx.x * 64, z = blockIdx.z;
    const bf16* Ahp = Ah + (long)z * a_z;
    const bf16* Alp = Al + (long)z * a_z;
    const bf16* Bhp = Bh + (long)z * b_z;
    const bf16* Blp = Bl + (long)z * b_z;

    const int ld_r = tid >> 3, ld_c = (tid & 7) * 8;
    const uint32_t s_wr = (uint32_t)(ld_r * TSTRIDE + ld_c * 2);

    const int a_r = (lane & 7) + ((lane >> 3) & 1) * 8;
    const int a_c8 = (lane >> 4) * 8;
    const uint32_t aoff = (uint32_t)((wm * 16 + a_r) * TSTRIDE + a_c8 * 2);
    const int b_r = (lane & 7) + (lane >> 4) * 8;
    const int b_c8 = ((lane >> 3) & 1) * 8;
    const uint32_t boff = (uint32_t)((wn * 16 + b_r) * TSTRIDE + b_c8 * 2);

    float acc[2][4];
#pragma unroll
    for (int j = 0; j < 2; j++)
#pragma unroll
        for (int q = 0; q < 4; q++) acc[j][q] = 0.f;

    uint32_t fah[2][4], fal[2][4], fbh[2][2][2], fbl[2][2][2];

    const int nch = K >> 6;

    auto issue = [&](int kk, int st){
        uint32_t base = sb + st * STAGE2 + s_wr;
        const bf16* ga0 = Ahp + (long)(m0 + ld_r) * lda + kk + ld_c;
        const bf16* ga1 = Alp + (long)(m0 + ld_r) * lda + kk + ld_c;
        const bf16* gb0 = Bhp + (long)(n0 + ld_r) * ldb + kk + ld_c;
        const bf16* gb1 = Blp + (long)(n0 + ld_r) * ldb + kk + ld_c;
        cpa16(base + OA_H2, ga0);
        cpa16(base + OA_L2, ga1);
        cpa16(base + OB_H2,                gb0);
        cpa16(base + OB_H2 + 32 * TSTRIDE, gb0 + 32 * ldb);
        cpa16(base + OB_L2,                gb1);
        cpa16(base + OB_L2 + 32 * TSTRIDE, gb1 + 32 * ldb);
        cpa_commit();
    };

    issue(0, 0);
    for (int i = 0; i < nch; i++) {
        if (i + 1 < nch) { issue((i + 1) << 6, (i + 1) & 1); cpa_wait<1>(); }
        else             { cpa_wait<0>(); }
        __syncthreads();

        uint32_t st = sb + (i & 1) * STAGE2;

        ldsm4(fbh[0][0][0], fbh[0][0][1], fbh[0][1][0], fbh[0][1][1], st + OB_H2 + boff);
        ldsm4(fbl[0][0][0], fbl[0][0][1], fbl[0][1][0], fbl[0][1][1], st + OB_L2 + boff);
        ldsm4(fah[0][0], fah[0][1], fah[0][2], fah[0][3], st + OA_H2 + aoff);
        ldsm4(fal[0][0], fal[0][1], fal[0][2], fal[0][3], st + OA_L2 + aoff);

#pragma unroll
        for (int ks = 0; ks < 4; ks++) {
            const int cur = ks & 1, nxt = cur ^ 1;
            if (ks < 3) {
                uint32_t kb = (ks + 1) * 32;
                ldsm4(fbh[nxt][0][0], fbh[nxt][0][1], fbh[nxt][1][0], fbh[nxt][1][1],
                      st + OB_H2 + boff + kb);
                ldsm4(fbl[nxt][0][0], fbl[nxt][0][1], fbl[nxt][1][0], fbl[nxt][1][1],
                      st + OB_L2 + boff + kb);
                ldsm4(fah[nxt][0], fah[nxt][1], fah[nxt][2], fah[nxt][3],
                      st + OA_H2 + aoff + kb);
                ldsm4(fal[nxt][0], fal[nxt][1], fal[nxt][2], fal[nxt][3],
                      st + OA_L2 + aoff + kb);
            }
#pragma unroll
            for (int nf = 0; nf < 2; nf++) mma16816(acc[nf], fah[cur], fbh[cur][nf]);
#pragma unroll
            for (int nf = 0; nf < 2; nf++) mma16816(acc[nf], fah[cur], fbl[cur][nf]);
#pragma unroll
            for (int nf = 0; nf < 2; nf++) mma16816(acc[nf], fal[cur], fbh[cur][nf]);
        }
        __syncthreads();
    }

    const int g = lane >> 2, tg = lane & 3;
    const float* bp = bias ? bias + (long)z * bias_z : nullptr;
    float* Cz = C ? C + (long)z * c_z : nullptr;
#pragma unroll
    for (int nf = 0; nf < 2; nf++) {
        int row = m0 + wm * 16 + g;
        int col = n0 + wn * 16 + nf * 8 + tg * 2;
        float v0 = acc[nf][0], v1 = acc[nf][1];
        float v2 = acc[nf][2], v3 = acc[nf][3];
        if (bp) {
            float bb0 = __ldg(bp + col), bb1 = __ldg(bp + col + 1);
            v0 += bb0; v1 += bb1; v2 += bb0; v3 += bb1;
        }
        if (flags & FL_RELU) {
            v0 = fmaxf(v0, 0.f); v1 = fmaxf(v1, 0.f);
            v2 = fmaxf(v2, 0.f); v3 = fmaxf(v3, 0.f);
        }
        if (flags & FL_F32) {
            *(float2*)&Cz[(long)row * ldc + col] = make_float2(v0, v1);
            *(float2*)&Cz[(long)(row + 8) * ldc + col] = make_float2(v2, v3);
        }
        if (flags & FL_HILO) {
            bf16 h0 = __float2bfloat16(v0), h1 = __float2bfloat16(v1);
            bf16 h2 = __float2bfloat16(v2), h3 = __float2bfloat16(v3);
            __nv_bfloat162 ph0; ph0.x = h0; ph0.y = h1;
            __nv_bfloat162 ph1; ph1.x = h2; ph1.y = h3;
            __nv_bfloat162 pl0, pl1;
            pl0.x = __float2bfloat16(v0 - __bfloat162float(h0));
            pl0.y = __float2bfloat16(v1 - __bfloat162float(h1));
            pl1.x = __float2bfloat16(v2 - __bfloat162float(h2));
            pl1.y = __float2bfloat16(v3 - __bfloat162float(h3));
            *(__nv_bfloat162*)&Ch[(long)row * ldch + col] = ph0;
            *(__nv_bfloat162*)&Cl[(long)row * ldch + col] = pl0;
            *(__nv_bfloat162*)&Ch[(long)(row + 8) * ldch + col] = ph1;
            *(__nv_bfloat162*)&Cl[(long)(row + 8) * ldch + col] = pl1;
        }
    }
}

// ========= wo GEMM (bf16 3-pass small-tile) + edges piggyback on idle SMs =========
__global__ void __launch_bounds__(256, 4)
wo_edges_k(const bf16* __restrict__ Ah, const bf16* __restrict__ Al,
           const bf16* __restrict__ Bh, const bf16* __restrict__ Bl,
           const float* __restrict__ bias,
           bf16* __restrict__ Ch, bf16* __restrict__ Cl,
           const float* __restrict__ attn, int* __restrict__ rel,
           int2* __restrict__ elist, int* __restrict__ ecnt)
{
    if (blockIdx.y >= 16) {
        // edges: head-mean + threshold + compact list (2 bu rows per block)
        int eb = (blockIdx.y - 16) * 8 + blockIdx.x;     // 0..255
        int t = threadIdx.x;
        int bu = eb * 2 + (t >> 7);
        int b = bu >> 7, u = bu & 127, v = t & 127;
        float s = 0.f;
#pragma unroll
        for (int h = 0; h < HH; h++)
            s += attn[(((long)(b * HH + h) * SS) + u) * SS + v];
        s *= 0.125f;
        long ridx = (long)bu * SS + v;
        rel[ridx] = 0;
        if ((s > THRESH) && (u != v)) {
            int p = atomicAdd(ecnt, 1);
            if (p < MAXE) elist[p] = make_int2(bu, v);
        }
        return;
    }

    extern __shared__ char sm[];
    uint32_t sb = smem_u32(sm);
    const int tid = threadIdx.x, lane = tid & 31, wid = tid >> 5;
    const int wm = wid >> 2, wn = wid & 3;
    const int m0 = blockIdx.y * 32, n0 = blockIdx.x * 64;

    const int ld_r = tid >> 3, ld_c = (tid & 7) * 8;
    const uint32_t s_wr = (uint32_t)(ld_r * TSTRIDE + ld_c * 2);

    const int a_r = (lane & 7) + ((lane >> 3) & 1) * 8;
    const int a_c8 = (lane >> 4) * 8;
    const uint32_t aoff = (uint32_t)((wm * 16 + a_r) * TSTRIDE + a_c8 * 2);
    const int b_r = (lane & 7) + (lane >> 4) * 8;
    const int b_c8 = ((lane >> 3) & 1) * 8;
    const uint32_t boff = (uint32_t)((wn * 16 + b_r) * TSTRIDE + b_c8 * 2);

    float acc[2][4];
#pragma unroll
    for (int j = 0; j < 2; j++)
#pragma unroll
        for (int q = 0; q < 4; q++) acc[j][q] = 0.f;

    uint32_t fah[2][4], fal[2][4], fbh[2][2][2], fbl[2][2][2];

    auto issue = [&](int kk, int st){
        uint32_t base = sb + st * STAGE2 + s_wr;
        const bf16* ga0 = Ah + (long)(m0 + ld_r) * DD + kk + ld_c;
        const bf16* ga1 = Al + (long)(m0 + ld_r) * DD + kk + ld_c;
        const bf16* gb0 = Bh + (long)(n0 + ld_r) * DD + kk + ld_c;
        const bf16* gb1 = Bl + (long)(n0 + ld_r) * DD + kk + ld_c;
        cpa16(base + OA_H2, ga0);
        cpa16(base + OA_L2, ga1);
        cpa16(base + OB_H2,                gb0);
        cpa16(base + OB_H2 + 32 * TSTRIDE, gb0 + 32 * DD);
        cpa16(base + OB_L2,                gb1);
        cpa16(base + OB_L2 + 32 * TSTRIDE, gb1 + 32 * DD);
        cpa_commit();
    };

    const int nch = DD >> 6;
    issue(0, 0);
    for (int i = 0; i < nch; i++) {
        if (i + 1 < nch) { issue((i + 1) << 6, (i + 1) & 1); cpa_wait<1>(); }
        else             { cpa_wait<0>(); }
        __syncthreads();

        uint32_t st = sb + (i & 1) * STAGE2;

        ldsm4(fbh[0][0][0], fbh[0][0][1], fbh[0][1][0], fbh[0][1][1], st + OB_H2 + boff);
        ldsm4(fbl[0][0][0], fbl[0][0][1], fbl[0][1][0], fbl[0][1][1], st + OB_L2 + boff);
        ldsm4(fah[0][0], fah[0][1], fah[0][2], fah[0][3], st + OA_H2 + aoff);
        ldsm4(fal[0][0], fal[0][1], fal[0][2], fal[0][3], st + OA_L2 + aoff);

#pragma unroll
        for (int ks = 0; ks < 4; ks++) {
            const int cur = ks & 1, nxt = cur ^ 1;
            if (ks < 3) {
                uint32_t kb = (ks + 1) * 32;
                ldsm4(fbh[nxt][0][0], fbh[nxt][0][1], fbh[nxt][1][0], fbh[nxt][1][1],
                      st + OB_H2 + boff + kb);
                ldsm4(fbl[nxt][0][0], fbl[nxt][0][1], fbl[nxt][1][0], fbl[nxt][1][1],
                      st + OB_L2 + boff + kb);
                ldsm4(fah[nxt][0], fah[nxt][1], fah[nxt][2], fah[nxt][3],
                      st + OA_H2 + aoff + kb);
                ldsm4(fal[nxt][0], fal[nxt][1], fal[nxt][2], fal[nxt][3],
                      st + OA_L2 + aoff + kb);
            }
#pragma unroll
            for (int nf = 0; nf < 2; nf++) mma16816(acc[nf], fah[cur], fbh[cur][nf]);
#pragma unroll
            for (int nf = 0; nf < 2; nf++) mma16816(acc[nf], fah[cur], fbl[cur][nf]);
#pragma unroll
            for (int nf = 0; nf < 2; nf++) mma16816(acc[nf], fal[cur], fbh[cur][nf]);
        }
        __syncthreads();
    }

    const int g = lane >> 2, tg = lane & 3;
#pragma unroll
    for (int nf = 0; nf < 2; nf++) {
        int row = m0 + wm * 16 + g;
        int col = n0 + wn * 16 + nf * 8 + tg * 2;
        float bb0 = __ldg(bias + col), bb1 = __ldg(bias + col + 1);
        float v0 = acc[nf][0] + bb0, v1 = acc[nf][1] + bb1;
        float v2 = acc[nf][2] + bb0, v3 = acc[nf][3] + bb1;
        bf16 h0 = __float2bfloat16(v0), h1 = __float2bfloat16(v1);
        bf16 h2 = __float2bfloat16(v2), h3 = __float2bfloat16(v3);
        __nv_bfloat162 ph0; ph0.x = h0; ph0.y = h1;
        __nv_bfloat162 ph1; ph1.x = h2; ph1.y = h3;
        __nv_bfloat162 pl0, pl1;
        pl0.x = __float2bfloat16(v0 - __bfloat162float(h0));
        pl0.y = __float2bfloat16(v1 - __bfloat162float(h1));
        pl1.x = __float2bfloat16(v2 - __bfloat162float(h2));
        pl1.y = __float2bfloat16(v3 - __bfloat162float(h3));
        *(__nv_bfloat162*)&Ch[(long)row * DD + col] = ph0;
        *(__nv_bfloat162*)&Cl[(long)row * DD + col] = pl0;
        *(__nv_bfloat162*)&Ch[(long)(row + 8) * DD + col] = ph1;
        *(__nv_bfloat162*)&Cl[(long)(row + 8) * DD + col] = pl1;
    }
}

// ============ fp16 SINGLE-pass GEMM, 32x64 CTA tile (continuous-path GEMMs) ============
#define HOA 0
#define HOB 4608
#define HSTAGE 13824
#define GSMH 27648

__global__ void __launch_bounds__(256, 4)
gemm_h1(const __half* __restrict__ A, const __half* __restrict__ B, long b_z,
        const float* __restrict__ bias, float* __restrict__ C, long c_z, int K)
{
    extern __shared__ char sm[];
    uint32_t sb = smem_u32(sm);
    const int tid = threadIdx.x, lane = tid & 31, wid = tid >> 5;
    const int wm = wid >> 2, wn = wid & 3;
    const int m0 = blockIdx.y * 32, n0 = blockIdx.x * 64, z = blockIdx.z;
    const __half* Bp = B + (long)z * b_z;

    const int ld_r = tid >> 3, ld_c = (tid & 7) * 8;
    const uint32_t s_wr = (uint32_t)(ld_r * TSTRIDE + ld_c * 2);

    const int a_r = (lane & 7) + ((lane >> 3) & 1) * 8;
    const int a_c8 = (lane >> 4) * 8;
    const uint32_t aoff = (uint32_t)((wm * 16 + a_r) * TSTRIDE + a_c8 * 2);
    const int b_r = (lane & 7) + (lane >> 4) * 8;
    const int b_c8 = ((lane >> 3) & 1) * 8;
    const uint32_t boff = (uint32_t)((wn * 16 + b_r) * TSTRIDE + b_c8 * 2);

    float acc[2][4];
#pragma unroll
    for (int j = 0; j < 2; j++)
#pragma unroll
        for (int q = 0; q < 4; q++) acc[j][q] = 0.f;

    uint32_t fa[2][4], fb[2][2][2];

    const int nch = K >> 6;

    auto issue = [&](int kk, int st){
        uint32_t base = sb + st * HSTAGE + s_wr;
        cpa16(base + HOA, A + (long)(m0 + ld_r) * K + kk + ld_c);
        const __half* gb = Bp + (long)(n0 + ld_r) * K + kk + ld_c;
        cpa16(base + HOB,                gb);
        cpa16(base + HOB + 32 * TSTRIDE, gb + 32 * K);
        cpa_commit();
    };

    issue(0, 0);
    for (int i = 0; i < nch; i++) {
        if (i + 1 < nch) { issue((i + 1) << 6, (i + 1) & 1); cpa_wait<1>(); }
        else             { cpa_wait<0>(); }
        __syncthreads();

        uint32_t st = sb + (i & 1) * HSTAGE;

        ldsm4(fb[0][0][0], fb[0][0][1], fb[0][1][0], fb[0][1][1], st + HOB + boff);
        ldsm4(fa[0][0], fa[0][1], fa[0][2], fa[0][3], st + HOA + aoff);

#pragma unroll
        for (int ks = 0; ks < 4; ks++) {
            const int cur = ks & 1, nxt = cur ^ 1;
            if (ks < 3) {
                uint32_t kb = (ks + 1) * 32;
                ldsm4(fb[nxt][0][0], fb[nxt][0][1], fb[nxt][1][0], fb[nxt][1][1],
                      st + HOB + boff + kb);
                ldsm4(fa[nxt][0], fa[nxt][1], fa[nxt][2], fa[nxt][3],
                      st + HOA + aoff + kb);
            }
#pragma unroll
            for (int nf = 0; nf < 2; nf++) mma16816h(acc[nf], fa[cur], fb[cur][nf]);
        }
        __syncthreads();
    }

    const int g = lane >> 2, tg = lane & 3;
    float* Cz = C + (long)z * c_z;
#pragma unroll
    for (int nf = 0; nf < 2; nf++) {
        int row = m0 + wm * 16 + g;
        int col = n0 + wn * 16 + nf * 8 + tg * 2;
        float v0 = acc[nf][0], v1 = acc[nf][1];
        float v2 = acc[nf][2], v3 = acc[nf][3];
        if (bias) {
            float bb0 = __ldg(bias + col), bb1 = __ldg(bias + col + 1);
            v0 += bb0; v1 += bb1; v2 += bb0; v3 += bb1;
        }
        *(float2*)&Cz[(long)row * DD + col] = make_float2(v0, v1);
        *(float2*)&Cz[(long)(row + 8) * DD + col] = make_float2(v2, v3);
    }
}

// ========= combined ab (bf16 3-pass, z<2) + kg (fp16 single, z>=2) =========
__global__ void __launch_bounds__(256, 4)
abkg_k(const bf16* __restrict__ nuh, const bf16* __restrict__ nul,
       const __half* __restrict__ nu16,
       const bf16* __restrict__ Wh, const bf16* __restrict__ Wl,   // rc bf16, unit z*UU
       const __half* __restrict__ Wkg,                              // kg fp16 base
       float* __restrict__ ab, float* __restrict__ trans)
{
    extern __shared__ char sm[];
    uint32_t sb = smem_u32(sm);
    const int tid = threadIdx.x, lane = tid & 31, wid = tid >> 5;
    const int wm = wid >> 2, wn = wid & 3;
    const int m0 = blockIdx.y * 32, n0 = blockIdx.x * 64, z = blockIdx.z;

    const int ld_r = tid >> 3, ld_c = (tid & 7) * 8;
    const uint32_t s_wr = (uint32_t)(ld_r * TSTRIDE + ld_c * 2);
    const int a_r = (lane & 7) + ((lane >> 3) & 1) * 8;
    const int a_c8 = (lane >> 4) * 8;
    const uint32_t aoff = (uint32_t)((wm * 16 + a_r) * TSTRIDE + a_c8 * 2);
    const int b_r = (lane & 7) + (lane >> 4) * 8;
    const int b_c8 = ((lane >> 3) & 1) * 8;
    const uint32_t boff = (uint32_t)((wn * 16 + b_r) * TSTRIDE + b_c8 * 2);
    const int g = lane >> 2, tg = lane & 3;
    const int nch = DD >> 6;

    if (z < 2) {
        // ---- bf16 3-pass (rc unit z) ----
        const bf16* Ahp = nuh;
        const bf16* Alp = nul;
        const bf16* Bhp = Wh + (long)z * UU;
        const bf16* Blp = Wl + (long)z * UU;

        float acc[2][4];
#pragma unroll
        for (int j = 0; j < 2; j++)
#pragma unroll
            for (int q = 0; q < 4; q++) acc[j][q] = 0.f;
        uint32_t fah[2][4], fal[2][4], fbh[2][2][2], fbl[2][2][2];

        auto issue = [&](int kk, int st){
            uint32_t base = sb + st * STAGE2 + s_wr;
            const bf16* ga0 = Ahp + (long)(m0 + ld_r) * DD + kk + ld_c;
            const bf16* ga1 = Alp + (long)(m0 + ld_r) * DD + kk + ld_c;
            const bf16* gb0 = Bhp + (long)(n0 + ld_r) * DD + kk + ld_c;
            const bf16* gb1 = Blp + (long)(n0 + ld_r) * DD + kk + ld_c;
            cpa16(base + OA_H2, ga0);
            cpa16(base + OA_L2, ga1);
            cpa16(base + OB_H2,                gb0);
            cpa16(base + OB_H2 + 32 * TSTRIDE, gb0 + 32 * DD);
            cpa16(base + OB_L2,                gb1);
            cpa16(base + OB_L2 + 32 * TSTRIDE, gb1 + 32 * DD);
            cpa_commit();
        };

        issue(0, 0);
        for (int i = 0; i < nch; i++) {
            if (i + 1 < nch) { issue((i + 1) << 6, (i + 1) & 1); cpa_wait<1>(); }
            else             { cpa_wait<0>(); }
            __syncthreads();
            uint32_t st = sb + (i & 1) * STAGE2;
            ldsm4(fbh[0][0][0], fbh[0][0][1], fbh[0][1][0], fbh[0][1][1], st + OB_H2 + boff);
            ldsm4(fbl[0][0][0], fbl[0][0][1], fbl[0][1][0], fbl[0][1][1], st + OB_L2 + boff);
            ldsm4(fah[0][0], fah[0][1], fah[0][2], fah[0][3], st + OA_H2 + aoff);
            ldsm4(fal[0][0], fal[0][1], fal[0][2], fal[0][3], st + OA_L2 + aoff);
#pragma unroll
            for (int ks = 0; ks < 4; ks++) {
                const int cur = ks & 1, nxt = cur ^ 1;
                if (ks < 3) {
                    uint32_t kb = (ks + 1) * 32;
                    ldsm4(fbh[nxt][0][0], fbh[nxt][0][1], fbh[nxt][1][0], fbh[nxt][1][1],
                          st + OB_H2 + boff + kb);
                    ldsm4(fbl[nxt][0][0], fbl[nxt][0][1], fbl[nxt][1][0], fbl[nxt][1][1],
                          st + OB_L2 + boff + kb);
                    ldsm4(fah[nxt][0], fah[nxt][1], fah[nxt][2], fah[nxt][3],
                          st + OA_H2 + aoff + kb);
                    ldsm4(fal[nxt][0], fal[nxt][1], fal[nxt][2], fal[nxt][3],
                          st + OA_L2 + aoff + kb);
                }
#pragma unroll
                for (int nf = 0; nf < 2; nf++) mma16816(acc[nf], fah[cur], fbh[cur][nf]);
#pragma unroll
                for (int nf = 0; nf < 2; nf++) mma16816(acc[nf], fah[cur], fbl[cur][nf]);
#pragma unroll
                for (int nf = 0; nf < 2; nf++) mma16816(acc[nf], fal[cur], fbh[cur][nf]);
            }
            __syncthreads();
        }

        float* Cz = ab + (long)z * UU;
#pragma unroll
        for (int nf = 0; nf < 2; nf++) {
            int row = m0 + wm * 16 + g;
            int col = n0 + wn * 16 + nf * 8 + tg * 2;
            *(float2*)&Cz[(long)row * DD + col] = make_float2(acc[nf][0], acc[nf][1]);
            *(float2*)&Cz[(long)(row + 8) * DD + col] = make_float2(acc[nf][2], acc[nf][3]);
        }
    } else {
        // ---- fp16 single pass (kg relation r = z-1) ----
        int r = z - 1;
        const __half* Bp = Wkg + (long)r * UU;

        float acc[2][4];
#pragma unroll
        for (int j = 0; j < 2; j++)
#pragma unroll
            for (int q = 0; q < 4; q++) acc[j][q] = 0.f;
        uint32_t fa[2][4], fb[2][2][2];

        auto issue = [&](int kk, int st){
            uint32_t base = sb + st * HSTAGE + s_wr;
            cpa16(base + HOA, nu16 + (long)(m0 + ld_r) * DD + kk + ld_c);
            const __half* gb = Bp + (long)(n0 + ld_r) * DD + kk + ld_c;
            cpa16(base + HOB,                gb);
            cpa16(base + HOB + 32 * TSTRIDE, gb + 32 * DD);
            cpa_commit();
        };

        issue(0, 0);
        for (int i = 0; i < nch; i++) {
            if (i + 1 < nch) { issue((i + 1) << 6, (i + 1) & 1); cpa_wait<1>(); }
            else             { cpa_wait<0>(); }
            __syncthreads();
            uint32_t st = sb + (i & 1) * HSTAGE;
            ldsm4(fb[0][0][0], fb[0][0][1], fb[0][1][0], fb[0][1][1], st + HOB + boff);
            ldsm4(fa[0][0], fa[0][1], fa[0][2], fa[0][3], st + HOA + aoff);
#pragma unroll
            for (int ks = 0; ks < 4; ks++) {
                const int cur = ks & 1, nxt = cur ^ 1;
                if (ks < 3) {
                    uint32_t kb = (ks + 1) * 32;
                    ldsm4(fb[nxt][0][0], fb[nxt][0][1], fb[nxt][1][0], fb[nxt][1][1],
                          st + HOB + boff + kb);
                    ldsm4(fa[nxt][0], fa[nxt][1], fa[nxt][2], fa[nxt][3],
                          st + HOA + aoff + kb);
                }
#pragma unroll
                for (int nf = 0; nf < 2; nf++) mma16816h(acc[nf], fa[cur], fb[cur][nf]);
            }
            __syncthreads();
        }

        float* Cz = trans + (long)r * UU;
#pragma unroll
        for (int nf = 0; nf < 2; nf++) {
            int row = m0 + wm * 16 + g;
            int col = n0 + wn * 16 + nf * 8 + tg * 2;
            *(float2*)&Cz[(long)row * DD + col] = make_float2(acc[nf][0], acc[nf][1]);
            *(float2*)&Cz[(long)(row + 8) * DD + col] = make_float2(acc[nf][2], acc[nf][3]);
        }
    }
}

// ======================= LayerNorm 2 (residual, fp32 out) =======================
__global__ void ln2_k(const float* __restrict__ in, const float* __restrict__ add,
                      const float* __restrict__ g, const float* __restrict__ b,
                      float* __restrict__ out)
{
    int row = blockIdx.x, t = threadIdx.x;
    __shared__ float rbuf[256];
    long base = (long)row * DD;
    float v0 = in[base + t] + add[base + t];
    float v1 = in[base + t + 256] + add[base + t + 256];
    rbuf[t] = v0 + v1; __syncthreads();
    for (int s = 128; s > 0; s >>= 1) { if (t < s) rbuf[t] += rbuf[t + s]; __syncthreads(); }
    float mean = rbuf[0] * (1.0f / 512.0f);
    __syncthreads();
    float d0 = v0 - mean, d1 = v1 - mean;
    rbuf[t] = d0 * d0 + d1 * d1; __syncthreads();
    for (int s = 128; s > 0; s >>= 1) { if (t < s) rbuf[t] += rbuf[t + s]; __syncthreads(); }
    float rs = rsqrtf(rbuf[0] * (1.0f / 512.0f) + 1e-5f);
    out[base + t]       = d0 * rs * g[t]       + b[t];
    out[base + t + 256] = d1 * rs * g[t + 256] + b[t + 256];
}

// ========== fused attention: scores + softmax + ctx, 16-row tiles ==========
__global__ void attn_fused_k(const float* __restrict__ q, const float* __restrict__ k,
                             const float* __restrict__ v, float* __restrict__ attn,
                             bf16* __restrict__ ch, bf16* __restrict__ cl)
{
    int it = blockIdx.x, h = blockIdx.y, b = blockIdx.z;  // 256 thr
    int t = threadIdx.x;
    int i0 = it * 16;
    __shared__ float ks[SS][DH + 1];
    __shared__ float qs[16][DH + 1];
    __shared__ float P[16][SS];
    const float* kbase = k + (long)b * SS * DD + h * DH;
    const float* qbase = q + (long)b * SS * DD + h * DH;
    for (int idx = t; idx < SS * DH; idx += 256) {
        int j = idx >> 6, d = idx & 63;
        ks[j][d] = kbase[(long)j * DD + d];
    }
    for (int idx = t; idx < 16 * DH; idx += 256) {
        int r = idx >> 6, d = idx & 63;
        qs[r][d] = qbase[(long)(i0 + r) * DD + d];
    }
    __syncthreads();
    {
        int j = t & 127, grp = t >> 7;
#pragma unroll
        for (int r = 0; r < 8; r++) {
            int i = grp * 8 + r;
            float acc = 0.f;
#pragma unroll
            for (int d = 0; d < DH; d++) acc += qs[i][d] * ks[j][d];
            P[i][j] = acc * 0.125f;
        }
    }
    __syncthreads();
    {
        int w = t >> 5, ln = t & 31;
        long obase = (((long)(b * HH + h) * SS) + i0) * SS;
#pragma unroll
        for (int rr = 0; rr < 2; rr++) {
            int i = w * 2 + rr;
            float m = -1e30f;
#pragma unroll
            for (int c = 0; c < 4; c++) m = fmaxf(m, P[i][ln + c * 32]);
#pragma unroll
            for (int o = 16; o > 0; o >>= 1) m = fmaxf(m, __shfl_xor_sync(0xffffffffu, m, o));
            float s = 0.f, e[4];
#pragma unroll
            for (int c = 0; c < 4; c++) { e[c] = expf(P[i][ln + c * 32] - m); s += e[c]; }
#pragma unroll
            for (int o = 16; o > 0; o >>= 1) s += __shfl_xor_sync(0xffffffffu, s, o);
            float inv = 1.0f / s;
#pragma unroll
            for (int c = 0; c < 4; c++) {
                float pv = e[c] * inv;
                P[i][ln + c * 32] = pv;
                attn[obase + (long)i * SS + ln + c * 32] = pv;
            }
        }
    }
    __syncthreads();
    const float* vbase = v + (long)b * SS * DD + h * DH;
    for (int idx = t; idx < SS * DH; idx += 256) {
        int j = idx >> 6, dd = idx & 63;
        ks[j][dd] = vbase[(long)j * DD + dd];
    }
    __syncthreads();
    {
        int d = t & 63, ig = t >> 6;
        float acc[4] = {0.f, 0.f, 0.f, 0.f};
#pragma unroll
        for (int jh = 0; jh < 2; jh++) {
            float vreg[64];
#pragma unroll
            for (int jj = 0; jj < 64; jj++) vreg[jj] = ks[jh * 64 + jj][d];
#pragma unroll
            for (int r = 0; r < 4; r++) {
                int i = ig + 4 * r;
                float a = acc[r];
#pragma unroll
                for (int jj = 0; jj < 64; jj++) a += P[i][jh * 64 + jj] * vreg[jj];
                acc[r] = a;
            }
        }
#pragma unroll
        for (int r = 0; r < 4; r++) {
            int i = ig + 4 * r;
            long o = (long)(b * SS + i0 + i) * DD + h * DH + d;
            bf16 hh = __float2bfloat16(acc[r]);
            ch[o] = hh; cl[o] = __float2bfloat16(acc[r] - __bfloat162float(hh));
        }
    }
}

// ======== pair classifier on compacted edges: one warp per edge ========
__global__ void __launch_bounds__(256)
pair2_k(const float* __restrict__ ap, const float* __restrict__ bp,
        const float* __restrict__ rc_b1, const float* __restrict__ rc_w2,
        const float* __restrict__ rc_b2,
        const int2* __restrict__ elist, const int* __restrict__ ecnt,
        int* __restrict__ rel)
{
    int total = *ecnt; if (total > MAXE) total = MAXE;
    int wg = blockIdx.x * 8 + (threadIdx.x >> 5);
    int nw = gridDim.x * 8;
    int lane = threadIdx.x & 31;

    for (int e = wg; e < total; e += nw) {
        int2 ed = elist[e];
        int bu = ed.x, v = ed.y;
        int bb = bu >> 7;
        const float* A = ap + (long)bu * DD;
        const float* B = bp + ((long)(bb * SS + v)) * DD;
        float acc[RR];
#pragma unroll
        for (int r = 0; r < RR; r++) acc[r] = 0.f;
#pragma unroll
        for (int c = 0; c < 4; c++) {
            int d = c * 128 + lane * 4;
            float4 a4 = *(const float4*)(A + d);
            float4 b4 = *(const float4*)(B + d);
            float4 c4 = *(const float4*)(rc_b1 + d);
            float hs[4];
            hs[0] = fmaxf(a4.x + b4.x + c4.x, 0.f);
            hs[1] = fmaxf(a4.y + b4.y + c4.y, 0.f);
            hs[2] = fmaxf(a4.z + b4.z + c4.z, 0.f);
            hs[3] = fmaxf(a4.w + b4.w + c4.w, 0.f);
#pragma unroll
            for (int j = 0; j < 4; j++) {
                float4 w0 = *(const float4*)(rc_w2 + (long)(d + j) * RR);
                float4 w1 = *(const float4*)(rc_w2 + (long)(d + j) * RR + 4);
                acc[0] += hs[j] * w0.x; acc[1] += hs[j] * w0.y;
                acc[2] += hs[j] * w0.z; acc[3] += hs[j] * w0.w;
                acc[4] += hs[j] * w1.x; acc[5] += hs[j] * w1.y;
                acc[6] += hs[j] * w1.z; acc[7] += hs[j] * w1.w;
            }
        }
#pragma unroll
        for (int r = 0; r < RR; r++)
#pragma unroll
            for (int o = 16; o > 0; o >>= 1)
                acc[r] += __shfl_xor_sync(0xffffffffu, acc[r], o);
        if (lane == 0) {
            int pred = 0; float best = acc[0] + rc_b2[0];
#pragma unroll
            for (int r = 1; r < RR; r++) {
                float lg = acc[r] + rc_b2[r];
                if (lg > best) { best = lg; pred = r; }
            }
            if (pred != 0) rel[(long)bu * SS + v] = pred;
        }
    }
}

// ============= nu: reduce split-K partials + bias + bf16 hi/lo + fp16 =============
__global__ void conv_nu_k(const float* __restrict__ P, const float* __restrict__ b2,
                          float* __restrict__ nu, bf16* __restrict__ H, bf16* __restrict__ L,
                          __half* __restrict__ N16)
{
    int row = blockIdx.x, t = threadIdx.x;  // 256
    for (int c = t; c < DD; c += 256) {
        long i = (long)row * DD + c;
        float v = b2[c] + P[i] + P[UU + i] + P[2L*UU + i] + P[3L*UU + i];
        nu[i] = v;
        bf16 h = __float2bfloat16(v);
        H[i] = h; L[i] = __float2bfloat16(v - __bfloat162float(h));
        N16[i] = __float2half(v);
    }
}

// ======================= edge aggregation (writes reasoned fp16) =======================
__global__ void agg_k(const int* __restrict__ rel, const float* __restrict__ trans,
                      const float* __restrict__ nu, __half* __restrict__ r16)
{
    int bv = blockIdx.x;                 // b*S + v
    int b = bv >> 7, v = bv & 127, t = threadIdx.x;   // 256
    __shared__ int sr[SS];
    if (t < SS) sr[t] = rel[((long)b * SS + t) * SS + v];
    __syncthreads();
    float a0 = 0.f, a1 = 0.f;
    for (int u = 0; u < SS; u++) {
        int r = sr[u];
        if (r) {
            const float* tr = trans + (long)r * UU + (long)(b * SS + u) * DD;
            a0 += tr[t]; a1 += tr[t + 256];
        }
    }
    long row = (long)bv * DD;
    r16[row + t]       = __float2half(nu[row + t] + a0);
    r16[row + t + 256] = __float2half(nu[row + t + 256] + a1);
}

// ======================= launch =======================
extern "C" void kernel_launch(void* const* d_in, const int* in_sizes, int n_in,
                              void* d_out, int out_size)
{
    const float* x     = (const float*)d_in[0];
    const float* ln1_g = (const float*)d_in[1];
    const float* ln1_b = (const float*)d_in[2];
    const float* wq    = (const float*)d_in[3];
    const float* bq    = (const float*)d_in[4];
    const float* wk    = (const float*)d_in[5];
    const float* bk    = (const float*)d_in[6];
    const float* wv    = (const float*)d_in[7];
    const float* bvv   = (const float*)d_in[8];
    const float* wo    = (const float*)d_in[9];
    const float* bo    = (const float*)d_in[10];
    const float* w1    = (const float*)d_in[11];
    const float* b1    = (const float*)d_in[12];
    const float* w2    = (const float*)d_in[13];
    const float* b2    = (const float*)d_in[14];
    const float* rc_w1 = (const float*)d_in[15];
    const float* rc_b1 = (const float*)d_in[16];
    const float* rc_w2 = (const float*)d_in[17];
    const float* rc_b2 = (const float*)d_in[18];
    const float* kg_w  = (const float*)d_in[19];
    const float* s2n_w = (const float*)d_in[20];
    const float* s2n_b = (const float*)d_in[21];
    const float* ln2_g = (const float*)d_in[22];
    const float* ln2_b = (const float*)d_in[23];
    float* out = (float*)d_out;

    bf16 *wTh, *wTl, *xnh, *xnl, *ctxh, *ctxl, *aoh, *aol, *hidh, *hidl, *nuh, *nul;
    __half *wT16, *nu16, *rs16;
    float *b3, *qkv, *attn, *nupart, *nu, *ab, *trans, *nr;
    int *rel, *ecnt;
    int2 *elist;
    cudaGetSymbolAddress((void**)&wTh, g_wTh);   cudaGetSymbolAddress((void**)&wTl, g_wTl);
    cudaGetSymbolAddress((void**)&wT16, g_wT16);
    cudaGetSymbolAddress((void**)&b3, g_b3);
    cudaGetSymbolAddress((void**)&xnh, g_xnh);   cudaGetSymbolAddress((void**)&xnl, g_xnl);
    cudaGetSymbolAddress((void**)&qkv, g_qkv);
    cudaGetSymbolAddress((void**)&attn, g_attn);
    cudaGetSymbolAddress((void**)&ctxh, g_ctxh); cudaGetSymbolAddress((void**)&ctxl, g_ctxl);
    cudaGetSymbolAddress((void**)&aoh, g_aoh);   cudaGetSymbolAddress((void**)&aol, g_aol);
    cudaGetSymbolAddress((void**)&hidh, g_hidh); cudaGetSymbolAddress((void**)&hidl, g_hidl);
    cudaGetSymbolAddress((void**)&nupart, g_nupart);
    cudaGetSymbolAddress((void**)&nu, g_nu);
    cudaGetSymbolAddress((void**)&nuh, g_nuh);   cudaGetSymbolAddress((void**)&nul, g_nul);
    cudaGetSymbolAddress((void**)&nu16, g_nu16);
    cudaGetSymbolAddress((void**)&ab, g_ab);
    cudaGetSymbolAddress((void**)&trans, g_trans);
    cudaGetSymbolAddress((void**)&rel, g_rel);
    cudaGetSymbolAddress((void**)&rs16, g_rs16);
    cudaGetSymbolAddress((void**)&nr, g_nr);
    cudaGetSymbolAddress((void**)&elist, g_elist);
    cudaGetSymbolAddress((void**)&ecnt, g_ecnt);

    cudaFuncSetAttribute(gemm_mma, cudaFuncAttributeMaxDynamicSharedMemorySize, GSM);
    cudaFuncSetAttribute(gemm_mma, cudaFuncAttributePreferredSharedMemoryCarveout, 100);
    cudaFuncSetAttribute(gemm_sm, cudaFuncAttributeMaxDynamicSharedMemorySize, GSM2);
    cudaFuncSetAttribute(gemm_sm, cudaFuncAttributePreferredSharedMemoryCarveout, 100);
    cudaFuncSetAttribute(gemm_h1, cudaFuncAttributeMaxDynamicSharedMemorySize, GSMH);
    cudaFuncSetAttribute(gemm_h1, cudaFuncAttributePreferredSharedMemoryCarveout, 100);
    cudaFuncSetAttribute(wo_edges_k, cudaFuncAttributeMaxDynamicSharedMemorySize, GSM2);
    cudaFuncSetAttribute(wo_edges_k, cudaFuncAttributePreferredSharedMemoryCarveout, 100);
    cudaFuncSetAttribute(abkg_k, cudaFuncAttributeMaxDynamicSharedMemorySize, GSM2);
    cudaFuncSetAttribute(abkg_k, cudaFuncAttributePreferredSharedMemoryCarveout, 100);

    // fused prep: weight transpose/convert + ln1 + bias pack + edge-counter reset
    prep_k<<<WBLK + BS, 256>>>(wq, wk, wv, wo, w1, w2, rc_w1, kg_w, s2n_w,
                               bq, bk, bvv, x, ln1_g, ln1_b, xnh, xnl);

    // QKV (z=3), fp32 out — small tile for 384 CTAs
    gemm_sm<<<dim3(8, 16, 3), 256, GSM2>>>(xnh, xnl, DD, 0, wTh, wTl, UU, DD,
                                           b3, DD, qkv, UU, DD, nullptr, nullptr, 0,
                                           DD, FL_F32);
    // fused attention (scores + softmax + ctx)
    attn_fused_k<<<dim3(8, HH, BB), 256>>>(qkv, qkv + UU, qkv + 2 * UU, attn, ctxh, ctxl);

    // ao = ctx @ wo + bo (bf16 3-pass) + edge extraction piggyback
    wo_edges_k<<<dim3(8, 48, 1), 256, GSM2>>>(ctxh, ctxl, wTh + 3L*UU, wTl + 3L*UU,
                                              bo, aoh, aol, attn, rel, elist, ecnt);

    // hid = relu(ao @ w1 + b1) (hi/lo only, N=2048) — big tile
    gemm_mma<<<dim3(32, 8, 1), 256, GSM>>>(aoh, aol, DD, 0, wTh + 4L*UU, wTl + 4L*UU, 0, DD,
                                           b1, 0, nullptr, 0, 0, hidh, hidl, FF,
                                           DD, FL_HILO | FL_RELU);
    // nu partials = hid @ w2  (split-K z=4 into 4 slabs)
    gemm_mma<<<dim3(8, 8, 4), 256, GSM>>>(hidh, hidl, FF, DD, wTh + 8L*UU, wTl + 8L*UU, DD, FF,
                                          nullptr, 0, nupart, UU, DD, nullptr, nullptr, 0,
                                          DD, FL_F32);
    conv_nu_k<<<BS, 256>>>(nupart, b2, nu, nuh, nul, nu16);

    // ab (bf16 3-pass, z<2) + kg (fp16 single, z=2..8) in ONE launch
    abkg_k<<<dim3(8, 16, 9), 256, GSM2>>>(nuh, nul, nu16,
                                          wTh + 12L*UU, wTl + 12L*UU, wT16, ab, trans);

    // relation classifier on compacted edges only
    pair2_k<<<64, 256>>>(ab, ab + UU, rc_b1, rc_w2, rc_b2, elist, ecnt, rel);

    // aggregation -> reasoned fp16
    agg_k<<<BS, 256>>>(rel, trans, nu, rs16);

    // s2n projection, fp16 single pass (continuous path)
    gemm_h1<<<dim3(8, 16, 1), 256, GSMH>>>(rs16, wT16 + 8L*UU, 0,
                                           s2n_b, nr, 0, DD);
    // final residual LN
    ln2_k<<<BS, 256>>>(nr, x, ln2_g, ln2_b, out);
}

// round 16
// speedup vs baseline: 1.0217x; 1.0217x over previous
#include <cuda_runtime.h>
#include <cuda_bf16.h>
#include <cuda_fp16.h>
#include <math.h>
#include <stdint.h>

#define BB 4
#define SS 128
#define DD 512
#define HH 8
#define DH 64
#define FF 2048
#define RR 8
#define BS (BB*SS)          // 512
#define UU 262144           // 512*512
#define THRESH 0.1f
#define MAXE 8192

typedef __nv_bfloat16 bf16;

// ======================= helpers =======================
__device__ __forceinline__ uint32_t smem_u32(const void* p){
    uint32_t a;
    asm("{ .reg .u64 t; cvta.to.shared.u64 t, %1; cvt.u32.u64 %0, t; }" : "=r"(a) : "l"(p));
    return a;
}
__device__ __forceinline__ void ldsm4(uint32_t& r0, uint32_t& r1, uint32_t& r2, uint32_t& r3,
                                      uint32_t addr){
    asm volatile("ldmatrix.sync.aligned.m8n8.x4.shared.b16 {%0,%1,%2,%3}, [%4];"
                 : "=r"(r0), "=r"(r1), "=r"(r2), "=r"(r3) : "r"(addr));
}
__device__ __forceinline__ void mma16816(float* d, const uint32_t* a, const uint32_t* b){
    asm volatile("mma.sync.aligned.m16n8k16.row.col.f32.bf16.bf16.f32 "
                 "{%0,%1,%2,%3}, {%4,%5,%6,%7}, {%8,%9}, {%0,%1,%2,%3};"
                 : "+f"(d[0]), "+f"(d[1]), "+f"(d[2]), "+f"(d[3])
                 : "r"(a[0]), "r"(a[1]), "r"(a[2]), "r"(a[3]), "r"(b[0]), "r"(b[1]));
}
__device__ __forceinline__ void mma16816h(float* d, const uint32_t* a, const uint32_t* b){
    asm volatile("mma.sync.aligned.m16n8k16.row.col.f32.f16.f16.f32 "
                 "{%0,%1,%2,%3}, {%4,%5,%6,%7}, {%8,%9}, {%0,%1,%2,%3};"
                 : "+f"(d[0]), "+f"(d[1]), "+f"(d[2]), "+f"(d[3])
                 : "r"(a[0]), "r"(a[1]), "r"(a[2]), "r"(a[3]), "r"(b[0]), "r"(b[1]));
}
__device__ __forceinline__ void cpa16(uint32_t s, const void* g){
    asm volatile("cp.async.cg.shared.global [%0], [%1], 16;" :: "r"(s), "l"(g));
}
__device__ __forceinline__ void cpa_commit(){
    asm volatile("cp.async.commit_group;" ::: "memory");
}
template<int N> __device__ __forceinline__ void cpa_wait(){
    asm volatile("cp.async.wait_group %0;" :: "n"(N) : "memory");
}

// ======================= scratch (device globals) =======================
__device__ bf16  g_wTh[14*UU];          // bf16 hi weights (units 0..13)
__device__ bf16  g_wTl[14*UU];          // bf16 lo weights
__device__ __half g_wT16[9*UU];         // fp16 weights: kg relations 0..7, s2n (unit 8)
__device__ float g_b3[3*DD];            // packed q/k/v biases
__device__ bf16  g_xnh[UU], g_xnl[UU];
__device__ float g_qkv[3*UU];
__device__ float g_attn[BB*HH*SS*SS];
__device__ bf16  g_ctxh[UU], g_ctxl[UU];
__device__ bf16  g_aoh[UU],  g_aol[UU];
__device__ bf16  g_hidh[BS*FF], g_hidl[BS*FF];
__device__ float g_nupart[4*UU];        // split-K partials for nu
__device__ float g_nu[UU];
__device__ bf16  g_nuh[UU], g_nul[UU];
__device__ __half g_nu16[UU];
__device__ float g_ab[2*UU];            // a/b parts
__device__ float g_trans[8*UU];         // RGCN transform slabs [r][n][d], r=1..7 used
__device__ int   g_rel[BB*SS*SS];
__device__ __half g_rs16[UU];           // reasoned, fp16
__device__ float g_nr[UU];
__device__ int2  g_elist[MAXE];
__device__ int   g_ecnt;

// ========== prep: fused weight transpose/convert + ln1 + bias pack + counter reset ==========
#define WBLK 5888

__global__ void prep_k(const float* __restrict__ wq, const float* __restrict__ wk,
                       const float* __restrict__ wv, const float* __restrict__ wo,
                       const float* __restrict__ w1, const float* __restrict__ w2,
                       const float* __restrict__ rc, const float* __restrict__ kg,
                       const float* __restrict__ s2n,
                       const float* __restrict__ bq, const float* __restrict__ bk,
                       const float* __restrict__ bvv,
                       const float* __restrict__ x, const float* __restrict__ g,
                       const float* __restrict__ b,
                       bf16* __restrict__ oh, bf16* __restrict__ ol)
{
    __shared__ float tile[32][33];
    __shared__ float rbuf[256];
    int bid = blockIdx.x, t = threadIdx.x;

    if (bid < WBLK) {
        int z = bid >> 8, rem = bid & 255;
        int bx = rem & 15, by = rem >> 4;
        const float* src; int ld; long dst; int dld;
        if (z < 3)       { const float* q3[3] = {wq, wk, wv};
                           src = q3[z]; ld = DD; dst = (long)z*UU; dld = DD; }
        else if (z == 3) { src = wo; ld = DD; dst = 3L*UU; dld = DD; }
        else if (z < 8)  { int u = z-4; src = w1 + u*DD; ld = FF; dst = 4L*UU + (long)u*UU; dld = DD; }
        else if (z < 12) { int u = z-8; src = w2 + (long)u*UU; ld = DD; dst = 8L*UU + (long)u*DD; dld = FF; }
        else if (z < 14) { int u = z-12; src = rc + (long)u*UU; ld = DD; dst = (12L+u)*UU; dld = DD; }
        else if (z < 22) { int u = z-14; src = kg + (long)u*UU; ld = DD; dst = (long)u*UU; dld = DD; }
        else             { src = s2n; ld = DD; dst = 8L*UU; dld = DD; }

        int k0 = by * 32, n0 = bx * 32;
        int tx = t & 31, ty = t >> 5;          // (32, 8)
#pragma unroll
        for (int i = 0; i < 4; i++)
            tile[ty + 8*i][tx] = __ldg(src + (long)(k0 + ty + 8*i) * ld + n0 + tx);
        __syncthreads();
        bool f16 = z >= 14;
#pragma unroll
        for (int i = 0; i < 2; i++) {
            int p = t + i * 256;
            int n = p >> 4, kp = p & 15;
            float v0 = tile[2*kp    ][n];
            float v1 = tile[2*kp + 1][n];
            long off = dst + (long)(n0 + n) * dld + k0 + 2*kp;
            if (f16) {
                __half2 ph; ph.x = __float2half(v0); ph.y = __float2half(v1);
                *(__half2*)&g_wT16[off] = ph;
            } else {
                bf16 h0 = __float2bfloat16(v0), h1 = __float2bfloat16(v1);
                __nv_bfloat162 ph; ph.x = h0; ph.y = h1;
                __nv_bfloat162 pl;
                pl.x = __float2bfloat16(v0 - __bfloat162float(h0));
                pl.y = __float2bfloat16(v1 - __bfloat162float(h1));
                *(__nv_bfloat162*)&g_wTh[off] = ph;
                *(__nv_bfloat162*)&g_wTl[off] = pl;
            }
        }
        return;
    }

    int row = bid - WBLK;                      // 0..511, ln1
    if (row == 0) {
        for (int i = t; i < DD; i += 256) {
            g_b3[i] = bq[i]; g_b3[DD+i] = bk[i]; g_b3[2*DD+i] = bvv[i];
        }
        if (t == 0) g_ecnt = 0;
    }
    long base = (long)row * DD;
    float v0 = x[base + t], v1 = x[base + t + 256];
    rbuf[t] = v0 + v1; __syncthreads();
    for (int s = 128; s > 0; s >>= 1) { if (t < s) rbuf[t] += rbuf[t + s]; __syncthreads(); }
    float mean = rbuf[0] * (1.0f / 512.0f);
    __syncthreads();
    float d0 = v0 - mean, d1 = v1 - mean;
    rbuf[t] = d0 * d0 + d1 * d1; __syncthreads();
    for (int s = 128; s > 0; s >>= 1) { if (t < s) rbuf[t] += rbuf[t + s]; __syncthreads(); }
    float rs = rsqrtf(rbuf[0] * (1.0f / 512.0f) + 1e-5f);
    float o0 = d0 * rs * g[t] + b[t];
    float o1 = d1 * rs * g[t + 256] + b[t + 256];
    bf16 h0 = __float2bfloat16(o0), h1 = __float2bfloat16(o1);
    oh[base + t] = h0;       ol[base + t]       = __float2bfloat16(o0 - __bfloat162float(h0));
    oh[base + t + 256] = h1; ol[base + t + 256] = __float2bfloat16(o1 - __bfloat162float(h1));
}

// ======================= mma.sync bf16 3-pass GEMM (64x64 tile, 2-stage) =======================
#define FL_F32  1
#define FL_HILO 2
#define FL_RELU 4

#define TSTRIDE 144
#define TILE_B  9216
#define STAGE_B 36864
#define GSM     73728

__global__ void __launch_bounds__(256, 3)
gemm_mma(const bf16* __restrict__ Ah, const bf16* __restrict__ Al, int lda, long a_z,
         const bf16* __restrict__ Bh, const bf16* __restrict__ Bl, long b_z, int ldb,
         const float* __restrict__ bias, int bias_z,
         float* __restrict__ C, long c_z, int ldc,
         bf16* __restrict__ Ch, bf16* __restrict__ Cl, int ldch,
         int K, int flags)
{
    extern __shared__ char sm[];
    uint32_t sb = smem_u32(sm);
    const int tid = threadIdx.x, lane = tid & 31, wid = tid >> 5;
    const int wm = wid >> 2, wn = wid & 3;
    const int m0 = blockIdx.y * 64, n0 = blockIdx.x * 64, z = blockIdx.z;
    const bf16* Ahp = Ah + (long)z * a_z;
    const bf16* Alp = Al + (long)z * a_z;
    const bf16* Bhp = Bh + (long)z * b_z;
    const bf16* Blp = Bl + (long)z * b_z;

    const int ld_r = tid >> 3, ld_c = (tid & 7) * 8;
    const uint32_t s_wr = (uint32_t)(ld_r * TSTRIDE + ld_c * 2);

    const int a_r = (lane & 7) + ((lane >> 3) & 1) * 8;
    const int a_c8 = (lane >> 4) * 8;
    const uint32_t aoff = (uint32_t)((wm * 32 + a_r) * TSTRIDE + a_c8 * 2);
    const int b_r = (lane & 7) + (lane >> 4) * 8;
    const int b_c8 = ((lane >> 3) & 1) * 8;
    const uint32_t boff = (uint32_t)((wn * 16 + b_r) * TSTRIDE + b_c8 * 2);

    float acc[2][2][4];
#pragma unroll
    for (int i = 0; i < 2; i++)
#pragma unroll
        for (int j = 0; j < 2; j++)
#pragma unroll
            for (int q = 0; q < 4; q++) acc[i][j][q] = 0.f;

    uint32_t fah[2][2][4], fal[2][2][4], fbh[2][2][2], fbl[2][2][2];

    const int nch = K >> 6;

    auto issue = [&](int kk, int st){
        uint32_t base = sb + st * STAGE_B + s_wr;
        const bf16* ga0 = Ahp + (long)(m0 + ld_r) * lda + kk + ld_c;
        const bf16* ga1 = Alp + (long)(m0 + ld_r) * lda + kk + ld_c;
        const bf16* gb0 = Bhp + (long)(n0 + ld_r) * ldb + kk + ld_c;
        const bf16* gb1 = Blp + (long)(n0 + ld_r) * ldb + kk + ld_c;
        cpa16(base,                         ga0);
        cpa16(base + 32 * TSTRIDE,          ga0 + 32 * lda);
        cpa16(base + TILE_B,                ga1);
        cpa16(base + TILE_B + 32 * TSTRIDE, ga1 + 32 * lda);
        cpa16(base + 2 * TILE_B,                gb0);
        cpa16(base + 2 * TILE_B + 32 * TSTRIDE, gb0 + 32 * ldb);
        cpa16(base + 3 * TILE_B,                gb1);
        cpa16(base + 3 * TILE_B + 32 * TSTRIDE, gb1 + 32 * ldb);
        cpa_commit();
    };

    issue(0, 0);
    for (int i = 0; i < nch; i++) {
        if (i + 1 < nch) { issue((i + 1) << 6, (i + 1) & 1); cpa_wait<1>(); }
        else             { cpa_wait<0>(); }
        __syncthreads();

        uint32_t st = sb + (i & 1) * STAGE_B;

        {
            ldsm4(fbh[0][0][0], fbh[0][0][1], fbh[0][1][0], fbh[0][1][1], st + 2*TILE_B + boff);
            ldsm4(fbl[0][0][0], fbl[0][0][1], fbl[0][1][0], fbl[0][1][1], st + 3*TILE_B + boff);
#pragma unroll
            for (int mf = 0; mf < 2; mf++)
                ldsm4(fah[0][mf][0], fah[0][mf][1], fah[0][mf][2], fah[0][mf][3],
                      st + aoff + mf * (16*TSTRIDE));
#pragma unroll
            for (int mf = 0; mf < 2; mf++)
                ldsm4(fal[0][mf][0], fal[0][mf][1], fal[0][mf][2], fal[0][mf][3],
                      st + TILE_B + aoff + mf * (16*TSTRIDE));
        }

#pragma unroll
        for (int ks = 0; ks < 4; ks++) {
            const int cur = ks & 1, nxt = cur ^ 1;
            if (ks < 3) {
                uint32_t kb = (ks + 1) * 32;
                ldsm4(fbh[nxt][0][0], fbh[nxt][0][1], fbh[nxt][1][0], fbh[nxt][1][1],
                      st + 2*TILE_B + boff + kb);
                ldsm4(fbl[nxt][0][0], fbl[nxt][0][1], fbl[nxt][1][0], fbl[nxt][1][1],
                      st + 3*TILE_B + boff + kb);
#pragma unroll
                for (int mf = 0; mf < 2; mf++)
                    ldsm4(fah[nxt][mf][0], fah[nxt][mf][1], fah[nxt][mf][2], fah[nxt][mf][3],
                          st + aoff + mf * (16*TSTRIDE) + kb);
#pragma unroll
                for (int mf = 0; mf < 2; mf++)
                    ldsm4(fal[nxt][mf][0], fal[nxt][mf][1], fal[nxt][mf][2], fal[nxt][mf][3],
                          st + TILE_B + aoff + mf * (16*TSTRIDE) + kb);
            }
#pragma unroll
            for (int mf = 0; mf < 2; mf++)
#pragma unroll
                for (int nf = 0; nf < 2; nf++) mma16816(acc[mf][nf], fah[cur][mf], fbh[cur][nf]);
#pragma unroll
            for (int mf = 0; mf < 2; mf++)
#pragma unroll
                for (int nf = 0; nf < 2; nf++) mma16816(acc[mf][nf], fah[cur][mf], fbl[cur][nf]);
#pragma unroll
            for (int mf = 0; mf < 2; mf++)
#pragma unroll
                for (int nf = 0; nf < 2; nf++) mma16816(acc[mf][nf], fal[cur][mf], fbh[cur][nf]);
        }
        __syncthreads();
    }

    const int g = lane >> 2, tg = lane & 3;
    const float* bp = bias ? bias + (long)z * bias_z : nullptr;
    float* Cz = C ? C + (long)z * c_z : nullptr;
#pragma unroll
    for (int mf = 0; mf < 2; mf++) {
#pragma unroll
        for (int nf = 0; nf < 2; nf++) {
            int row = m0 + wm * 32 + mf * 16 + g;
            int col = n0 + wn * 16 + nf * 8 + tg * 2;
            float v0 = acc[mf][nf][0], v1 = acc[mf][nf][1];
            float v2 = acc[mf][nf][2], v3 = acc[mf][nf][3];
            if (bp) {
                float bb0 = __ldg(bp + col), bb1 = __ldg(bp + col + 1);
                v0 += bb0; v1 += bb1; v2 += bb0; v3 += bb1;
            }
            if (flags & FL_RELU) {
                v0 = fmaxf(v0, 0.f); v1 = fmaxf(v1, 0.f);
                v2 = fmaxf(v2, 0.f); v3 = fmaxf(v3, 0.f);
            }
            if (flags & FL_F32) {
                *(float2*)&Cz[(long)row * ldc + col] = make_float2(v0, v1);
                *(float2*)&Cz[(long)(row + 8) * ldc + col] = make_float2(v2, v3);
            }
            if (flags & FL_HILO) {
                bf16 h0 = __float2bfloat16(v0), h1 = __float2bfloat16(v1);
                bf16 h2 = __float2bfloat16(v2), h3 = __float2bfloat16(v3);
                __nv_bfloat162 ph0; ph0.x = h0; ph0.y = h1;
                __nv_bfloat162 ph1; ph1.x = h2; ph1.y = h3;
                __nv_bfloat162 pl0, pl1;
                pl0.x = __float2bfloat16(v0 - __bfloat162float(h0));
                pl0.y = __float2bfloat16(v1 - __bfloat162float(h1));
                pl1.x = __float2bfloat16(v2 - __bfloat162float(h2));
                pl1.y = __float2bfloat16(v3 - __bfloat162float(h3));
                *(__nv_bfloat162*)&Ch[(long)row * ldch + col] = ph0;
                *(__nv_bfloat162*)&Cl[(long)row * ldch + col] = pl0;
                *(__nv_bfloat162*)&Ch[(long)(row + 8) * ldch + col] = ph1;
                *(__nv_bfloat162*)&Cl[(long)(row + 8) * ldch + col] = pl1;
            }
        }
    }
}

// ============ small-tile bf16 variant: 32x64 CTA tile ============
#define OA_H2 0
#define OA_L2 4608
#define OB_H2 9216
#define OB_L2 18432
#define STAGE2 27648
#define GSM2 55296

__global__ void __launch_bounds__(256, 4)
gemm_sm(const bf16* __restrict__ Ah, const bf16* __restrict__ Al, int lda, long a_z,
        const bf16* __restrict__ Bh, const bf16* __restrict__ Bl, long b_z, int ldb,
        const float* __restrict__ bias, int bias_z,
        float* __restrict__ C, long c_z, int ldc,
        bf16* __restrict__ Ch, bf16* __restrict__ Cl, int ldch,
        int K, int flags)
{
    extern __shared__ char sm[];
    uint32_t sb = smem_u32(sm);
    const int tid = threadIdx.x, lane = tid & 31, wid = tid >> 5;
    const int wm = wid >> 2, wn = wid & 3;
    const int m0 = blockIdx.y * 32, n0 = blockIdx.x * 64, z = blockIdx.z;
    const bf16* Ahp = Ah + (long)z * a_z;
    const bf16* Alp = Al + (long)z * a_z;
    const bf16* Bhp = Bh + (long)z * b_z;
    const bf16* Blp = Bl + (long)z * b_z;

    const int ld_r = tid >> 3, ld_c = (tid & 7) * 8;
    const uint32_t s_wr = (uint32_t)(ld_r * TSTRIDE + ld_c * 2);

    const int a_r = (lane & 7) + ((lane >> 3) & 1) * 8;
    const int a_c8 = (lane >> 4) * 8;
    const uint32_t aoff = (uint32_t)((wm * 16 + a_r) * TSTRIDE + a_c8 * 2);
    const int b_r = (lane & 7) + (lane >> 4) * 8;
    const int b_c8 = ((lane >> 3) & 1) * 8;
    const uint32_t boff = (uint32_t)((wn * 16 + b_r) * TSTRIDE + b_c8 * 2);

    float acc[2][4];
#pragma unroll
    for (int j = 0; j < 2; j++)
#pragma unroll
        for (int q = 0; q < 4; q++) acc[j][q] = 0.f;

    uint32_t fah[2][4], fal[2][4], fbh[2][2][2], fbl[2][2][2];

    const int nch = K >> 6;

    auto issue = [&](int kk, int st){
        uint32_t base = sb + st * STAGE2 + s_wr;
        const bf16* ga0 = Ahp + (long)(m0 + ld_r) * lda + kk + ld_c;
        const bf16* ga1 = Alp + (long)(m0 + ld_r) * lda + kk + ld_c;
        const bf16* gb0 = Bhp + (long)(n0 + ld_r) * ldb + kk + ld_c;
        const bf16* gb1 = Blp + (long)(n0 + ld_r) * ldb + kk + ld_c;
        cpa16(base + OA_H2, ga0);
        cpa16(base + OA_L2, ga1);
        cpa16(base + OB_H2,                gb0);
        cpa16(base + OB_H2 + 32 * TSTRIDE, gb0 + 32 * ldb);
        cpa16(base + OB_L2,                gb1);
        cpa16(base + OB_L2 + 32 * TSTRIDE, gb1 + 32 * ldb);
        cpa_commit();
    };

    issue(0, 0);
    for (int i = 0; i < nch; i++) {
        if (i + 1 < nch) { issue((i + 1) << 6, (i + 1) & 1); cpa_wait<1>(); }
        else             { cpa_wait<0>(); }
        __syncthreads();

        uint32_t st = sb + (i & 1) * STAGE2;

        ldsm4(fbh[0][0][0], fbh[0][0][1], fbh[0][1][0], fbh[0][1][1], st + OB_H2 + boff);
        ldsm4(fbl[0][0][0], fbl[0][0][1], fbl[0][1][0], fbl[0][1][1], st + OB_L2 + boff);
        ldsm4(fah[0][0], fah[0][1], fah[0][2], fah[0][3], st + OA_H2 + aoff);
        ldsm4(fal[0][0], fal[0][1], fal[0][2], fal[0][3], st + OA_L2 + aoff);

#pragma unroll
        for (int ks = 0; ks < 4; ks++) {
            const int cur = ks & 1, nxt = cur ^ 1;
            if (ks < 3) {
                uint32_t kb = (ks + 1) * 32;
                ldsm4(fbh[nxt][0][0], fbh[nxt][0][1], fbh[nxt][1][0], fbh[nxt][1][1],
                      st + OB_H2 + boff + kb);
                ldsm4(fbl[nxt][0][0], fbl[nxt][0][1], fbl[nxt][1][0], fbl[nxt][1][1],
                      st + OB_L2 + boff + kb);
                ldsm4(fah[nxt][0], fah[nxt][1], fah[nxt][2], fah[nxt][3],
                      st + OA_H2 + aoff + kb);
                ldsm4(fal[nxt][0], fal[nxt][1], fal[nxt][2], fal[nxt][3],
                      st + OA_L2 + aoff + kb);
            }
#pragma unroll
            for (int nf = 0; nf < 2; nf++) mma16816(acc[nf], fah[cur], fbh[cur][nf]);
#pragma unroll
            for (int nf = 0; nf < 2; nf++) mma16816(acc[nf], fah[cur], fbl[cur][nf]);
#pragma unroll
            for (int nf = 0; nf < 2; nf++) mma16816(acc[nf], fal[cur], fbh[cur][nf]);
        }
        __syncthreads();
    }

    const int g = lane >> 2, tg = lane & 3;
    const float* bp = bias ? bias + (long)z * bias_z : nullptr;
    float* Cz = C ? C + (long)z * c_z : nullptr;
#pragma unroll
    for (int nf = 0; nf < 2; nf++) {
        int row = m0 + wm * 16 + g;
        int col = n0 + wn * 16 + nf * 8 + tg * 2;
        float v0 = acc[nf][0], v1 = acc[nf][1];
        float v2 = acc[nf][2], v3 = acc[nf][3];
        if (bp) {
            float bb0 = __ldg(bp + col), bb1 = __ldg(bp + col + 1);
            v0 += bb0; v1 += bb1; v2 += bb0; v3 += bb1;
        }
        if (flags & FL_RELU) {
            v0 = fmaxf(v0, 0.f); v1 = fmaxf(v1, 0.f);
            v2 = fmaxf(v2, 0.f); v3 = fmaxf(v3, 0.f);
        }
        if (flags & FL_F32) {
            *(float2*)&Cz[(long)row * ldc + col] = make_float2(v0, v1);
            *(float2*)&Cz[(long)(row + 8) * ldc + col] = make_float2(v2, v3);
        }
        if (flags & FL_HILO) {
            bf16 h0 = __float2bfloat16(v0), h1 = __float2bfloat16(v1);
            bf16 h2 = __float2bfloat16(v2), h3 = __float2bfloat16(v3);
            __nv_bfloat162 ph0; ph0.x = h0; ph0.y = h1;
            __nv_bfloat162 ph1; ph1.x = h2; ph1.y = h3;
            __nv_bfloat162 pl0, pl1;
            pl0.x = __float2bfloat16(v0 - __bfloat162float(h0));
            pl0.y = __float2bfloat16(v1 - __bfloat162float(h1));
            pl1.x = __float2bfloat16(v2 - __bfloat162float(h2));
            pl1.y = __float2bfloat16(v3 - __bfloat162float(h3));
            *(__nv_bfloat162*)&Ch[(long)row * ldch + col] = ph0;
            *(__nv_bfloat162*)&Cl[(long)row * ldch + col] = pl0;
            *(__nv_bfloat162*)&Ch[(long)(row + 8) * ldch + col] = ph1;
            *(__nv_bfloat162*)&Cl[(long)(row + 8) * ldch + col] = pl1;
        }
    }
}

// ============ fp16 SINGLE-pass GEMM, 32x64 CTA tile (continuous-path GEMMs) ============
#define HOA 0
#define HOB 4608
#define HSTAGE 13824
#define GSMH 27648

__global__ void __launch_bounds__(256, 4)
gemm_h1(const __half* __restrict__ A, const __half* __restrict__ B, long b_z,
        const float* __restrict__ bias, float* __restrict__ C, long c_z, int K)
{
    extern __shared__ char sm[];
    uint32_t sb = smem_u32(sm);
    const int tid = threadIdx.x, lane = tid & 31, wid = tid >> 5;
    const int wm = wid >> 2, wn = wid & 3;
    const int m0 = blockIdx.y * 32, n0 = blockIdx.x * 64, z = blockIdx.z;
    const __half* Bp = B + (long)z * b_z;

    const int ld_r = tid >> 3, ld_c = (tid & 7) * 8;
    const uint32_t s_wr = (uint32_t)(ld_r * TSTRIDE + ld_c * 2);

    const int a_r = (lane & 7) + ((lane >> 3) & 1) * 8;
    const int a_c8 = (lane >> 4) * 8;
    const uint32_t aoff = (uint32_t)((wm * 16 + a_r) * TSTRIDE + a_c8 * 2);
    const int b_r = (lane & 7) + (lane >> 4) * 8;
    const int b_c8 = ((lane >> 3) & 1) * 8;
    const uint32_t boff = (uint32_t)((wn * 16 + b_r) * TSTRIDE + b_c8 * 2);

    float acc[2][4];
#pragma unroll
    for (int j = 0; j < 2; j++)
#pragma unroll
        for (int q = 0; q < 4; q++) acc[j][q] = 0.f;

    uint32_t fa[2][4], fb[2][2][2];

    const int nch = K >> 6;

    auto issue = [&](int kk, int st){
        uint32_t base = sb + st * HSTAGE + s_wr;
        cpa16(base + HOA, A + (long)(m0 + ld_r) * K + kk + ld_c);
        const __half* gb = Bp + (long)(n0 + ld_r) * K + kk + ld_c;
        cpa16(base + HOB,                gb);
        cpa16(base + HOB + 32 * TSTRIDE, gb + 32 * K);
        cpa_commit();
    };

    issue(0, 0);
    for (int i = 0; i < nch; i++) {
        if (i + 1 < nch) { issue((i + 1) << 6, (i + 1) & 1); cpa_wait<1>(); }
        else             { cpa_wait<0>(); }
        __syncthreads();

        uint32_t st = sb + (i & 1) * HSTAGE;

        ldsm4(fb[0][0][0], fb[0][0][1], fb[0][1][0], fb[0][1][1], st + HOB + boff);
        ldsm4(fa[0][0], fa[0][1], fa[0][2], fa[0][3], st + HOA + aoff);

#pragma unroll
        for (int ks = 0; ks < 4; ks++) {
            const int cur = ks & 1, nxt = cur ^ 1;
            if (ks < 3) {
                uint32_t kb = (ks + 1) * 32;
                ldsm4(fb[nxt][0][0], fb[nxt][0][1], fb[nxt][1][0], fb[nxt][1][1],
                      st + HOB + boff + kb);
                ldsm4(fa[nxt][0], fa[nxt][1], fa[nxt][2], fa[nxt][3],
                      st + HOA + aoff + kb);
            }
#pragma unroll
            for (int nf = 0; nf < 2; nf++) mma16816h(acc[nf], fa[cur], fb[cur][nf]);
        }
        __syncthreads();
    }

    const int g = lane >> 2, tg = lane & 3;
    float* Cz = C + (long)z * c_z;
#pragma unroll
    for (int nf = 0; nf < 2; nf++) {
        int row = m0 + wm * 16 + g;
        int col = n0 + wn * 16 + nf * 8 + tg * 2;
        float v0 = acc[nf][0], v1 = acc[nf][1];
        float v2 = acc[nf][2], v3 = acc[nf][3];
        if (bias) {
            float bb0 = __ldg(bias + col), bb1 = __ldg(bias + col + 1);
            v0 += bb0; v1 += bb1; v2 += bb0; v3 += bb1;
        }
        *(float2*)&Cz[(long)row * DD + col] = make_float2(v0, v1);
        *(float2*)&Cz[(long)(row + 8) * DD + col] = make_float2(v2, v3);
    }
}

// ========= combined ab (bf16 3-pass, z<2) + kg (fp16 single, z>=2) =========
__global__ void __launch_bounds__(256, 4)
abkg_k(const bf16* __restrict__ nuh, const bf16* __restrict__ nul,
       const __half* __restrict__ nu16,
       const bf16* __restrict__ Wh, const bf16* __restrict__ Wl,
       const __half* __restrict__ Wkg,
       float* __restrict__ ab, float* __restrict__ trans)
{
    extern __shared__ char sm[];
    uint32_t sb = smem_u32(sm);
    const int tid = threadIdx.x, lane = tid & 31, wid = tid >> 5;
    const int wm = wid >> 2, wn = wid & 3;
    const int m0 = blockIdx.y * 32, n0 = blockIdx.x * 64, z = blockIdx.z;

    const int ld_r = tid >> 3, ld_c = (tid & 7) * 8;
    const uint32_t s_wr = (uint32_t)(ld_r * TSTRIDE + ld_c * 2);
    const int a_r = (lane & 7) + ((lane >> 3) & 1) * 8;
    const int a_c8 = (lane >> 4) * 8;
    const uint32_t aoff = (uint32_t)((wm * 16 + a_r) * TSTRIDE + a_c8 * 2);
    const int b_r = (lane & 7) + (lane >> 4) * 8;
    const int b_c8 = ((lane >> 3) & 1) * 8;
    const uint32_t boff = (uint32_t)((wn * 16 + b_r) * TSTRIDE + b_c8 * 2);
    const int g = lane >> 2, tg = lane & 3;
    const int nch = DD >> 6;

    if (z < 2) {
        const bf16* Ahp = nuh;
        const bf16* Alp = nul;
        const bf16* Bhp = Wh + (long)z * UU;
        const bf16* Blp = Wl + (long)z * UU;

        float acc[2][4];
#pragma unroll
        for (int j = 0; j < 2; j++)
#pragma unroll
            for (int q = 0; q < 4; q++) acc[j][q] = 0.f;
        uint32_t fah[2][4], fal[2][4], fbh[2][2][2], fbl[2][2][2];

        auto issue = [&](int kk, int st){
            uint32_t base = sb + st * STAGE2 + s_wr;
            const bf16* ga0 = Ahp + (long)(m0 + ld_r) * DD + kk + ld_c;
            const bf16* ga1 = Alp + (long)(m0 + ld_r) * DD + kk + ld_c;
            const bf16* gb0 = Bhp + (long)(n0 + ld_r) * DD + kk + ld_c;
            const bf16* gb1 = Blp + (long)(n0 + ld_r) * DD + kk + ld_c;
            cpa16(base + OA_H2, ga0);
            cpa16(base + OA_L2, ga1);
            cpa16(base + OB_H2,                gb0);
            cpa16(base + OB_H2 + 32 * TSTRIDE, gb0 + 32 * DD);
            cpa16(base + OB_L2,                gb1);
            cpa16(base + OB_L2 + 32 * TSTRIDE, gb1 + 32 * DD);
            cpa_commit();
        };

        issue(0, 0);
        for (int i = 0; i < nch; i++) {
            if (i + 1 < nch) { issue((i + 1) << 6, (i + 1) & 1); cpa_wait<1>(); }
            else             { cpa_wait<0>(); }
            __syncthreads();
            uint32_t st = sb + (i & 1) * STAGE2;
            ldsm4(fbh[0][0][0], fbh[0][0][1], fbh[0][1][0], fbh[0][1][1], st + OB_H2 + boff);
            ldsm4(fbl[0][0][0], fbl[0][0][1], fbl[0][1][0], fbl[0][1][1], st + OB_L2 + boff);
            ldsm4(fah[0][0], fah[0][1], fah[0][2], fah[0][3], st + OA_H2 + aoff);
            ldsm4(fal[0][0], fal[0][1], fal[0][2], fal[0][3], st + OA_L2 + aoff);
#pragma unroll
            for (int ks = 0; ks < 4; ks++) {
                const int cur = ks & 1, nxt = cur ^ 1;
                if (ks < 3) {
                    uint32_t kb = (ks + 1) * 32;
                    ldsm4(fbh[nxt][0][0], fbh[nxt][0][1], fbh[nxt][1][0], fbh[nxt][1][1],
                          st + OB_H2 + boff + kb);
                    ldsm4(fbl[nxt][0][0], fbl[nxt][0][1], fbl[nxt][1][0], fbl[nxt][1][1],
                          st + OB_L2 + boff + kb);
                    ldsm4(fah[nxt][0], fah[nxt][1], fah[nxt][2], fah[nxt][3],
                          st + OA_H2 + aoff + kb);
                    ldsm4(fal[nxt][0], fal[nxt][1], fal[nxt][2], fal[nxt][3],
                          st + OA_L2 + aoff + kb);
                }
#pragma unroll
                for (int nf = 0; nf < 2; nf++) mma16816(acc[nf], fah[cur], fbh[cur][nf]);
#pragma unroll
                for (int nf = 0; nf < 2; nf++) mma16816(acc[nf], fah[cur], fbl[cur][nf]);
#pragma unroll
                for (int nf = 0; nf < 2; nf++) mma16816(acc[nf], fal[cur], fbh[cur][nf]);
            }
            __syncthreads();
        }

        float* Cz = ab + (long)z * UU;
#pragma unroll
        for (int nf = 0; nf < 2; nf++) {
            int row = m0 + wm * 16 + g;
            int col = n0 + wn * 16 + nf * 8 + tg * 2;
            *(float2*)&Cz[(long)row * DD + col] = make_float2(acc[nf][0], acc[nf][1]);
            *(float2*)&Cz[(long)(row + 8) * DD + col] = make_float2(acc[nf][2], acc[nf][3]);
        }
    } else {
        int r = z - 1;
        const __half* Bp = Wkg + (long)r * UU;

        float acc[2][4];
#pragma unroll
        for (int j = 0; j < 2; j++)
#pragma unroll
            for (int q = 0; q < 4; q++) acc[j][q] = 0.f;
        uint32_t fa[2][4], fb[2][2][2];

        auto issue = [&](int kk, int st){
            uint32_t base = sb + st * HSTAGE + s_wr;
            cpa16(base + HOA, nu16 + (long)(m0 + ld_r) * DD + kk + ld_c);
            const __half* gb = Bp + (long)(n0 + ld_r) * DD + kk + ld_c;
            cpa16(base + HOB,                gb);
            cpa16(base + HOB + 32 * TSTRIDE, gb + 32 * DD);
            cpa_commit();
        };

        issue(0, 0);
        for (int i = 0; i < nch; i++) {
            if (i + 1 < nch) { issue((i + 1) << 6, (i + 1) & 1); cpa_wait<1>(); }
            else             { cpa_wait<0>(); }
            __syncthreads();
            uint32_t st = sb + (i & 1) * HSTAGE;
            ldsm4(fb[0][0][0], fb[0][0][1], fb[0][1][0], fb[0][1][1], st + HOB + boff);
            ldsm4(fa[0][0], fa[0][1], fa[0][2], fa[0][3], st + HOA + aoff);
#pragma unroll
            for (int ks = 0; ks < 4; ks++) {
                const int cur = ks & 1, nxt = cur ^ 1;
                if (ks < 3) {
                    uint32_t kb = (ks + 1) * 32;
                    ldsm4(fb[nxt][0][0], fb[nxt][0][1], fb[nxt][1][0], fb[nxt][1][1],
                          st + HOB + boff + kb);
                    ldsm4(fa[nxt][0], fa[nxt][1], fa[nxt][2], fa[nxt][3],
                          st + HOA + aoff + kb);
                }
#pragma unroll
                for (int nf = 0; nf < 2; nf++) mma16816h(acc[nf], fa[cur], fb[cur][nf]);
            }
            __syncthreads();
        }

        float* Cz = trans + (long)r * UU;
#pragma unroll
        for (int nf = 0; nf < 2; nf++) {
            int row = m0 + wm * 16 + g;
            int col = n0 + wn * 16 + nf * 8 + tg * 2;
            *(float2*)&Cz[(long)row * DD + col] = make_float2(acc[nf][0], acc[nf][1]);
            *(float2*)&Cz[(long)(row + 8) * DD + col] = make_float2(acc[nf][2], acc[nf][3]);
        }
    }
}

// ======================= LayerNorm 2 (residual, fp32 out) =======================
__global__ void ln2_k(const float* __restrict__ in, const float* __restrict__ add,
                      const float* __restrict__ g, const float* __restrict__ b,
                      float* __restrict__ out)
{
    int row = blockIdx.x, t = threadIdx.x;
    __shared__ float rbuf[256];
    long base = (long)row * DD;
    float v0 = in[base + t] + add[base + t];
    float v1 = in[base + t + 256] + add[base + t + 256];
    rbuf[t] = v0 + v1; __syncthreads();
    for (int s = 128; s > 0; s >>= 1) { if (t < s) rbuf[t] += rbuf[t + s]; __syncthreads(); }
    float mean = rbuf[0] * (1.0f / 512.0f);
    __syncthreads();
    float d0 = v0 - mean, d1 = v1 - mean;
    rbuf[t] = d0 * d0 + d1 * d1; __syncthreads();
    for (int s = 128; s > 0; s >>= 1) { if (t < s) rbuf[t] += rbuf[t + s]; __syncthreads(); }
    float rs = rsqrtf(rbuf[0] * (1.0f / 512.0f) + 1e-5f);
    out[base + t]       = d0 * rs * g[t]       + b[t];
    out[base + t + 256] = d1 * rs * g[t + 256] + b[t + 256];
}

// ========== fused attention: scores + softmax + ctx, 16-row tiles ==========
__global__ void attn_fused_k(const float* __restrict__ q, const float* __restrict__ k,
                             const float* __restrict__ v, float* __restrict__ attn,
                             bf16* __restrict__ ch, bf16* __restrict__ cl)
{
    int it = blockIdx.x, h = blockIdx.y, b = blockIdx.z;  // 256 thr
    int t = threadIdx.x;
    int i0 = it * 16;
    __shared__ float ks[SS][DH + 1];
    __shared__ float qs[16][DH + 1];
    __shared__ float P[16][SS];
    const float* kbase = k + (long)b * SS * DD + h * DH;
    const float* qbase = q + (long)b * SS * DD + h * DH;
    for (int idx = t; idx < SS * DH; idx += 256) {
        int j = idx >> 6, d = idx & 63;
        ks[j][d] = kbase[(long)j * DD + d];
    }
    for (int idx = t; idx < 16 * DH; idx += 256) {
        int r = idx >> 6, d = idx & 63;
        qs[r][d] = qbase[(long)(i0 + r) * DD + d];
    }
    __syncthreads();
    {
        int j = t & 127, grp = t >> 7;
#pragma unroll
        for (int r = 0; r < 8; r++) {
            int i = grp * 8 + r;
            float acc = 0.f;
#pragma unroll
            for (int d = 0; d < DH; d++) acc += qs[i][d] * ks[j][d];
            P[i][j] = acc * 0.125f;
        }
    }
    __syncthreads();
    {
        int w = t >> 5, ln = t & 31;
        long obase = (((long)(b * HH + h) * SS) + i0) * SS;
#pragma unroll
        for (int rr = 0; rr < 2; rr++) {
            int i = w * 2 + rr;
            float m = -1e30f;
#pragma unroll
            for (int c = 0; c < 4; c++) m = fmaxf(m, P[i][ln + c * 32]);
#pragma unroll
            for (int o = 16; o > 0; o >>= 1) m = fmaxf(m, __shfl_xor_sync(0xffffffffu, m, o));
            float s = 0.f, e[4];
#pragma unroll
            for (int c = 0; c < 4; c++) { e[c] = expf(P[i][ln + c * 32] - m); s += e[c]; }
#pragma unroll
            for (int o = 16; o > 0; o >>= 1) s += __shfl_xor_sync(0xffffffffu, s, o);
            float inv = 1.0f / s;
#pragma unroll
            for (int c = 0; c < 4; c++) {
                float pv = e[c] * inv;
                P[i][ln + c * 32] = pv;
                attn[obase + (long)i * SS + ln + c * 32] = pv;
            }
        }
    }
    __syncthreads();
    const float* vbase = v + (long)b * SS * DD + h * DH;
    for (int idx = t; idx < SS * DH; idx += 256) {
        int j = idx >> 6, dd = idx & 63;
        ks[j][dd] = vbase[(long)j * DD + dd];
    }
    __syncthreads();
    {
        int d = t & 63, ig = t >> 6;
        float acc[4] = {0.f, 0.f, 0.f, 0.f};
#pragma unroll
        for (int jh = 0; jh < 2; jh++) {
            float vreg[64];
#pragma unroll
            for (int jj = 0; jj < 64; jj++) vreg[jj] = ks[jh * 64 + jj][d];
#pragma unroll
            for (int r = 0; r < 4; r++) {
                int i = ig + 4 * r;
                float a = acc[r];
#pragma unroll
                for (int jj = 0; jj < 64; jj++) a += P[i][jh * 64 + jj] * vreg[jj];
                acc[r] = a;
            }
        }
#pragma unroll
        for (int r = 0; r < 4; r++) {
            int i = ig + 4 * r;
            long o = (long)(b * SS + i0 + i) * DD + h * DH + d;
            bf16 hh = __float2bfloat16(acc[r]);
            ch[o] = hh; cl[o] = __float2bfloat16(acc[r] - __bfloat162float(hh));
        }
    }
}

// ======== edges: head-mean + threshold + compact edge list ========
__global__ void edges_k(const float* __restrict__ attn, int* __restrict__ rel,
                        int2* __restrict__ elist, int* __restrict__ ecnt)
{
    int bu = blockIdx.x;                 // b*S + u
    int b = bu >> 7, u = bu & 127, v = threadIdx.x;  // 128 thr
    float s = 0.f;
#pragma unroll
    for (int h = 0; h < HH; h++)
        s += attn[(((long)(b * HH + h) * SS) + u) * SS + v];
    s *= 0.125f;
    long ridx = (long)bu * SS + v;
    rel[ridx] = 0;
    if ((s > THRESH) && (u != v)) {
        int p = atomicAdd(ecnt, 1);
        if (p < MAXE) elist[p] = make_int2(bu, v);
    }
}

// ======== pair classifier on compacted edges: one warp per edge ========
__global__ void __launch_bounds__(256)
pair2_k(const float* __restrict__ ap, const float* __restrict__ bp,
        const float* __restrict__ rc_b1, const float* __restrict__ rc_w2,
        const float* __restrict__ rc_b2,
        const int2* __restrict__ elist, const int* __restrict__ ecnt,
        int* __restrict__ rel)
{
    int total = *ecnt; if (total > MAXE) total = MAXE;
    int wg = blockIdx.x * 8 + (threadIdx.x >> 5);
    int nw = gridDim.x * 8;
    int lane = threadIdx.x & 31;

    for (int e = wg; e < total; e += nw) {
        int2 ed = elist[e];
        int bu = ed.x, v = ed.y;
        int bb = bu >> 7;
        const float* A = ap + (long)bu * DD;
        const float* B = bp + ((long)(bb * SS + v)) * DD;
        float acc[RR];
#pragma unroll
        for (int r = 0; r < RR; r++) acc[r] = 0.f;
#pragma unroll
        for (int c = 0; c < 4; c++) {
            int d = c * 128 + lane * 4;
            float4 a4 = *(const float4*)(A + d);
            float4 b4 = *(const float4*)(B + d);
            float4 c4 = *(const float4*)(rc_b1 + d);
            float hs[4];
            hs[0] = fmaxf(a4.x + b4.x + c4.x, 0.f);
            hs[1] = fmaxf(a4.y + b4.y + c4.y, 0.f);
            hs[2] = fmaxf(a4.z + b4.z + c4.z, 0.f);
            hs[3] = fmaxf(a4.w + b4.w + c4.w, 0.f);
#pragma unroll
            for (int j = 0; j < 4; j++) {
                float4 w0 = *(const float4*)(rc_w2 + (long)(d + j) * RR);
                float4 w1 = *(const float4*)(rc_w2 + (long)(d + j) * RR + 4);
                acc[0] += hs[j] * w0.x; acc[1] += hs[j] * w0.y;
                acc[2] += hs[j] * w0.z; acc[3] += hs[j] * w0.w;
                acc[4] += hs[j] * w1.x; acc[5] += hs[j] * w1.y;
                acc[6] += hs[j] * w1.z; acc[7] += hs[j] * w1.w;
            }
        }
#pragma unroll
        for (int r = 0; r < RR; r++)
#pragma unroll
            for (int o = 16; o > 0; o >>= 1)
                acc[r] += __shfl_xor_sync(0xffffffffu, acc[r], o);
        if (lane == 0) {
            int pred = 0; float best = acc[0] + rc_b2[0];
#pragma unroll
            for (int r = 1; r < RR; r++) {
                float lg = acc[r] + rc_b2[r];
                if (lg > best) { best = lg; pred = r; }
            }
            if (pred != 0) rel[(long)bu * SS + v] = pred;
        }
    }
}

// ============= nu: reduce split-K partials + bias + bf16 hi/lo + fp16 =============
__global__ void conv_nu_k(const float* __restrict__ P, const float* __restrict__ b2,
                          float* __restrict__ nu, bf16* __restrict__ H, bf16* __restrict__ L,
                          __half* __restrict__ N16)
{
    int row = blockIdx.x, t = threadIdx.x;  // 256
    for (int c = t; c < DD; c += 256) {
        long i = (long)row * DD + c;
        float v = b2[c] + P[i] + P[UU + i] + P[2L*UU + i] + P[3L*UU + i];
        nu[i] = v;
        bf16 h = __float2bfloat16(v);
        H[i] = h; L[i] = __float2bfloat16(v - __bfloat162float(h));
        N16[i] = __float2half(v);
    }
}

// ======================= edge aggregation (writes reasoned fp16) =======================
__global__ void agg_k(const int* __restrict__ rel, const float* __restrict__ trans,
                      const float* __restrict__ nu, __half* __restrict__ r16)
{
    int bv = blockIdx.x;                 // b*S + v
    int b = bv >> 7, v = bv & 127, t = threadIdx.x;   // 256
    __shared__ int sr[SS];
    if (t < SS) sr[t] = rel[((long)b * SS + t) * SS + v];
    __syncthreads();
    float a0 = 0.f, a1 = 0.f;
    for (int u = 0; u < SS; u++) {
        int r = sr[u];
        if (r) {
            const float* tr = trans + (long)r * UU + (long)(b * SS + u) * DD;
            a0 += tr[t]; a1 += tr[t + 256];
        }
    }
    long row = (long)bv * DD;
    r16[row + t]       = __float2half(nu[row + t] + a0);
    r16[row + t + 256] = __float2half(nu[row + t + 256] + a1);
}

// ======================= launch =======================
extern "C" void kernel_launch(void* const* d_in, const int* in_sizes, int n_in,
                              void* d_out, int out_size)
{
    const float* x     = (const float*)d_in[0];
    const float* ln1_g = (const float*)d_in[1];
    const float* ln1_b = (const float*)d_in[2];
    const float* wq    = (const float*)d_in[3];
    const float* bq    = (const float*)d_in[4];
    const float* wk    = (const float*)d_in[5];
    const float* bk    = (const float*)d_in[6];
    const float* wv    = (const float*)d_in[7];
    const float* bvv   = (const float*)d_in[8];
    const float* wo    = (const float*)d_in[9];
    const float* bo    = (const float*)d_in[10];
    const float* w1    = (const float*)d_in[11];
    const float* b1    = (const float*)d_in[12];
    const float* w2    = (const float*)d_in[13];
    const float* b2    = (const float*)d_in[14];
    const float* rc_w1 = (const float*)d_in[15];
    const float* rc_b1 = (const float*)d_in[16];
    const float* rc_w2 = (const float*)d_in[17];
    const float* rc_b2 = (const float*)d_in[18];
    const float* kg_w  = (const float*)d_in[19];
    const float* s2n_w = (const float*)d_in[20];
    const float* s2n_b = (const float*)d_in[21];
    const float* ln2_g = (const float*)d_in[22];
    const float* ln2_b = (const float*)d_in[23];
    float* out = (float*)d_out;

    bf16 *wTh, *wTl, *xnh, *xnl, *ctxh, *ctxl, *aoh, *aol, *hidh, *hidl, *nuh, *nul;
    __half *wT16, *nu16, *rs16;
    float *b3, *qkv, *attn, *nupart, *nu, *ab, *trans, *nr;
    int *rel, *ecnt;
    int2 *elist;
    cudaGetSymbolAddress((void**)&wTh, g_wTh);   cudaGetSymbolAddress((void**)&wTl, g_wTl);
    cudaGetSymbolAddress((void**)&wT16, g_wT16);
    cudaGetSymbolAddress((void**)&b3, g_b3);
    cudaGetSymbolAddress((void**)&xnh, g_xnh);   cudaGetSymbolAddress((void**)&xnl, g_xnl);
    cudaGetSymbolAddress((void**)&qkv, g_qkv);
    cudaGetSymbolAddress((void**)&attn, g_attn);
    cudaGetSymbolAddress((void**)&ctxh, g_ctxh); cudaGetSymbolAddress((void**)&ctxl, g_ctxl);
    cudaGetSymbolAddress((void**)&aoh, g_aoh);   cudaGetSymbolAddress((void**)&aol, g_aol);
    cudaGetSymbolAddress((void**)&hidh, g_hidh); cudaGetSymbolAddress((void**)&hidl, g_hidl);
    cudaGetSymbolAddress((void**)&nupart, g_nupart);
    cudaGetSymbolAddress((void**)&nu, g_nu);
    cudaGetSymbolAddress((void**)&nuh, g_nuh);   cudaGetSymbolAddress((void**)&nul, g_nul);
    cudaGetSymbolAddress((void**)&nu16, g_nu16);
    cudaGetSymbolAddress((void**)&ab, g_ab);
    cudaGetSymbolAddress((void**)&trans, g_trans);
    cudaGetSymbolAddress((void**)&rel, g_rel);
    cudaGetSymbolAddress((void**)&rs16, g_rs16);
    cudaGetSymbolAddress((void**)&nr, g_nr);
    cudaGetSymbolAddress((void**)&elist, g_elist);
    cudaGetSymbolAddress((void**)&ecnt, g_ecnt);

    cudaFuncSetAttribute(gemm_mma, cudaFuncAttributeMaxDynamicSharedMemorySize, GSM);
    cudaFuncSetAttribute(gemm_mma, cudaFuncAttributePreferredSharedMemoryCarveout, 100);
    cudaFuncSetAttribute(gemm_sm, cudaFuncAttributeMaxDynamicSharedMemorySize, GSM2);
    cudaFuncSetAttribute(gemm_sm, cudaFuncAttributePreferredSharedMemoryCarveout, 100);
    cudaFuncSetAttribute(gemm_h1, cudaFuncAttributeMaxDynamicSharedMemorySize, GSMH);
    cudaFuncSetAttribute(gemm_h1, cudaFuncAttributePreferredSharedMemoryCarveout, 100);
    cudaFuncSetAttribute(abkg_k, cudaFuncAttributeMaxDynamicSharedMemorySize, GSM2);
    cudaFuncSetAttribute(abkg_k, cudaFuncAttributePreferredSharedMemoryCarveout, 100);

    // fused prep: weight transpose/convert + ln1 + bias pack + edge-counter reset
    prep_k<<<WBLK + BS, 256>>>(wq, wk, wv, wo, w1, w2, rc_w1, kg_w, s2n_w,
                               bq, bk, bvv, x, ln1_g, ln1_b, xnh, xnl);

    // QKV (z=3), fp32 out — small tile for 384 CTAs
    gemm_sm<<<dim3(8, 16, 3), 256, GSM2>>>(xnh, xnl, DD, 0, wTh, wTl, UU, DD,
                                           b3, DD, qkv, UU, DD, nullptr, nullptr, 0,
                                           DD, FL_F32);
    // fused attention (scores + softmax + ctx) + edge extraction
    attn_fused_k<<<dim3(8, HH, BB), 256>>>(qkv, qkv + UU, qkv + 2 * UU, attn, ctxh, ctxl);
    edges_k<<<BS, 128>>>(attn, rel, elist, ecnt);

    // ao = ctx @ wo + bo  (hi/lo only) — small tile
    gemm_sm<<<dim3(8, 16, 1), 256, GSM2>>>(ctxh, ctxl, DD, 0, wTh + 3L*UU, wTl + 3L*UU, 0, DD,
                                           bo, 0, nullptr, 0, 0, aoh, aol, DD,
                                           DD, FL_HILO);
    // hid = relu(ao @ w1 + b1) (hi/lo only, N=2048) — big tile
    gemm_mma<<<dim3(32, 8, 1), 256, GSM>>>(aoh, aol, DD, 0, wTh + 4L*UU, wTl + 4L*UU, 0, DD,
                                           b1, 0, nullptr, 0, 0, hidh, hidl, FF,
                                           DD, FL_HILO | FL_RELU);
    // nu partials = hid @ w2  (split-K z=4 into 4 slabs)
    gemm_mma<<<dim3(8, 8, 4), 256, GSM>>>(hidh, hidl, FF, DD, wTh + 8L*UU, wTl + 8L*UU, DD, FF,
                                          nullptr, 0, nupart, UU, DD, nullptr, nullptr, 0,
                                          DD, FL_F32);
    conv_nu_k<<<BS, 256>>>(nupart, b2, nu, nuh, nul, nu16);

    // ab (bf16 3-pass, z<2) + kg (fp16 single, z=2..8) in ONE launch
    abkg_k<<<dim3(8, 16, 9), 256, GSM2>>>(nuh, nul, nu16,
                                          wTh + 12L*UU, wTl + 12L*UU, wT16, ab, trans);

    // relation classifier on compacted edges only
    pair2_k<<<64, 256>>>(ab, ab + UU, rc_b1, rc_w2, rc_b2, elist, ecnt, rel);

    // aggregation -> reasoned fp16
    agg_k<<<BS, 256>>>(rel, trans, nu, rs16);

    // s2n projection, fp16 single pass (continuous path)
    gemm_h1<<<dim3(8, 16, 1), 256, GSMH>>>(rs16, wT16 + 8L*UU, 0,
                                           s2n_b, nr, 0, DD);
    // final residual LN
    ln2_k<<<BS, 256>>>(nr, x, ln2_g, ln2_b, out);
}

// round 17
// speedup vs baseline: 1.0347x; 1.0128x over previous
#include <cuda_runtime.h>
#include <cuda_bf16.h>
#include <cuda_fp16.h>
#include <math.h>
#include <stdint.h>

#define BB 4
#define SS 128
#define DD 512
#define HH 8
#define DH 64
#define FF 2048
#define RR 8
#define BS (BB*SS)          // 512
#define UU 262144           // 512*512
#define THRESH 0.1f
#define MAXE 8192

typedef __nv_bfloat16 bf16;

// ======================= helpers =======================
__device__ __forceinline__ uint32_t smem_u32(const void* p){
    uint32_t a;
    asm("{ .reg .u64 t; cvta.to.shared.u64 t, %1; cvt.u32.u64 %0, t; }" : "=r"(a) : "l"(p));
    return a;
}
__device__ __forceinline__ void ldsm4(uint32_t& r0, uint32_t& r1, uint32_t& r2, uint32_t& r3,
                                      uint32_t addr){
    asm volatile("ldmatrix.sync.aligned.m8n8.x4.shared.b16 {%0,%1,%2,%3}, [%4];"
                 : "=r"(r0), "=r"(r1), "=r"(r2), "=r"(r3) : "r"(addr));
}
__device__ __forceinline__ void mma16816(float* d, const uint32_t* a, const uint32_t* b){
    asm volatile("mma.sync.aligned.m16n8k16.row.col.f32.bf16.bf16.f32 "
                 "{%0,%1,%2,%3}, {%4,%5,%6,%7}, {%8,%9}, {%0,%1,%2,%3};"
                 : "+f"(d[0]), "+f"(d[1]), "+f"(d[2]), "+f"(d[3])
                 : "r"(a[0]), "r"(a[1]), "r"(a[2]), "r"(a[3]), "r"(b[0]), "r"(b[1]));
}
__device__ __forceinline__ void mma16816h(float* d, const uint32_t* a, const uint32_t* b){
    asm volatile("mma.sync.aligned.m16n8k16.row.col.f32.f16.f16.f32 "
                 "{%0,%1,%2,%3}, {%4,%5,%6,%7}, {%8,%9}, {%0,%1,%2,%3};"
                 : "+f"(d[0]), "+f"(d[1]), "+f"(d[2]), "+f"(d[3])
                 : "r"(a[0]), "r"(a[1]), "r"(a[2]), "r"(a[3]), "r"(b[0]), "r"(b[1]));
}
__device__ __forceinline__ void cpa16(uint32_t s, const void* g){
    asm volatile("cp.async.cg.shared.global [%0], [%1], 16;" :: "r"(s), "l"(g));
}
__device__ __forceinline__ void cpa_commit(){
    asm volatile("cp.async.commit_group;" ::: "memory");
}
template<int N> __device__ __forceinline__ void cpa_wait(){
    asm volatile("cp.async.wait_group %0;" :: "n"(N) : "memory");
}

// ======================= scratch (device globals) =======================
__device__ bf16  g_wTh[14*UU];          // bf16 hi weights (units 0..13)
__device__ bf16  g_wTl[14*UU];          // bf16 lo weights
__device__ __half g_wT16[9*UU];         // fp16 weights: kg relations 0..7, s2n (unit 8)
__device__ float g_b3[3*DD];            // packed q/k/v biases
__device__ bf16  g_xnh[UU], g_xnl[UU];
__device__ float g_qkv[3*UU];
__device__ float g_attn[BB*HH*SS*SS];
__device__ bf16  g_ctxh[UU], g_ctxl[UU];
__device__ bf16  g_aoh[UU],  g_aol[UU];
__device__ bf16  g_hidh[BS*FF], g_hidl[BS*FF];
__device__ float g_nupart[4*UU];        // split-K partials for nu
__device__ float g_nu[UU];
__device__ bf16  g_nuh[UU], g_nul[UU];
__device__ __half g_nu16[UU];
__device__ float g_ab[2*UU];            // a/b parts
__device__ float g_trans[8*UU];         // RGCN transform slabs [r][n][d], r=1..7 used
__device__ int   g_rel[BB*SS*SS];
__device__ __half g_rs16[UU];           // reasoned, fp16
__device__ float g_nr[UU];
__device__ int2  g_elist[MAXE];
__device__ int   g_ecnt;

// ========== prep: fused weight transpose/convert + ln1 + bias pack + counter reset ==========
#define WBLK 5888

__global__ void prep_k(const float* __restrict__ wq, const float* __restrict__ wk,
                       const float* __restrict__ wv, const float* __restrict__ wo,
                       const float* __restrict__ w1, const float* __restrict__ w2,
                       const float* __restrict__ rc, const float* __restrict__ kg,
                       const float* __restrict__ s2n,
                       const float* __restrict__ bq, const float* __restrict__ bk,
                       const float* __restrict__ bvv,
                       const float* __restrict__ x, const float* __restrict__ g,
                       const float* __restrict__ b,
                       bf16* __restrict__ oh, bf16* __restrict__ ol)
{
    __shared__ float tile[32][33];
    __shared__ float rbuf[256];
    int bid = blockIdx.x, t = threadIdx.x;

    if (bid < WBLK) {
        int z = bid >> 8, rem = bid & 255;
        int bx = rem & 15, by = rem >> 4;
        const float* src; int ld; long dst; int dld;
        if (z < 3)       { const float* q3[3] = {wq, wk, wv};
                           src = q3[z]; ld = DD; dst = (long)z*UU; dld = DD; }
        else if (z == 3) { src = wo; ld = DD; dst = 3L*UU; dld = DD; }
        else if (z < 8)  { int u = z-4; src = w1 + u*DD; ld = FF; dst = 4L*UU + (long)u*UU; dld = DD; }
        else if (z < 12) { int u = z-8; src = w2 + (long)u*UU; ld = DD; dst = 8L*UU + (long)u*DD; dld = FF; }
        else if (z < 14) { int u = z-12; src = rc + (long)u*UU; ld = DD; dst = (12L+u)*UU; dld = DD; }
        else if (z < 22) { int u = z-14; src = kg + (long)u*UU; ld = DD; dst = (long)u*UU; dld = DD; }
        else             { src = s2n; ld = DD; dst = 8L*UU; dld = DD; }

        int k0 = by * 32, n0 = bx * 32;
        int tx = t & 31, ty = t >> 5;          // (32, 8)
#pragma unroll
        for (int i = 0; i < 4; i++)
            tile[ty + 8*i][tx] = __ldg(src + (long)(k0 + ty + 8*i) * ld + n0 + tx);
        __syncthreads();
        bool f16 = z >= 14;
#pragma unroll
        for (int i = 0; i < 2; i++) {
            int p = t + i * 256;
            int n = p >> 4, kp = p & 15;
            float v0 = tile[2*kp    ][n];
            float v1 = tile[2*kp + 1][n];
            long off = dst + (long)(n0 + n) * dld + k0 + 2*kp;
            if (f16) {
                __half2 ph; ph.x = __float2half(v0); ph.y = __float2half(v1);
                *(__half2*)&g_wT16[off] = ph;
            } else {
                bf16 h0 = __float2bfloat16(v0), h1 = __float2bfloat16(v1);
                __nv_bfloat162 ph; ph.x = h0; ph.y = h1;
                __nv_bfloat162 pl;
                pl.x = __float2bfloat16(v0 - __bfloat162float(h0));
                pl.y = __float2bfloat16(v1 - __bfloat162float(h1));
                *(__nv_bfloat162*)&g_wTh[off] = ph;
                *(__nv_bfloat162*)&g_wTl[off] = pl;
            }
        }
        return;
    }

    int row = bid - WBLK;                      // 0..511, ln1
    if (row == 0) {
        for (int i = t; i < DD; i += 256) {
            g_b3[i] = bq[i]; g_b3[DD+i] = bk[i]; g_b3[2*DD+i] = bvv[i];
        }
        if (t == 0) g_ecnt = 0;
    }
    long base = (long)row * DD;
    float v0 = x[base + t], v1 = x[base + t + 256];
    rbuf[t] = v0 + v1; __syncthreads();
    for (int s = 128; s > 0; s >>= 1) { if (t < s) rbuf[t] += rbuf[t + s]; __syncthreads(); }
    float mean = rbuf[0] * (1.0f / 512.0f);
    __syncthreads();
    float d0 = v0 - mean, d1 = v1 - mean;
    rbuf[t] = d0 * d0 + d1 * d1; __syncthreads();
    for (int s = 128; s > 0; s >>= 1) { if (t < s) rbuf[t] += rbuf[t + s]; __syncthreads(); }
    float rs = rsqrtf(rbuf[0] * (1.0f / 512.0f) + 1e-5f);
    float o0 = d0 * rs * g[t] + b[t];
    float o1 = d1 * rs * g[t + 256] + b[t + 256];
    bf16 h0 = __float2bfloat16(o0), h1 = __float2bfloat16(o1);
    oh[base + t] = h0;       ol[base + t]       = __float2bfloat16(o0 - __bfloat162float(h0));
    oh[base + t + 256] = h1; ol[base + t + 256] = __float2bfloat16(o1 - __bfloat162float(h1));
}

// ======================= mma.sync bf16 3-pass GEMM (64x64 tile, 2-stage) =======================
#define FL_F32  1
#define FL_HILO 2
#define FL_RELU 4

#define TSTRIDE 144
#define TILE_B  9216
#define STAGE_B 36864
#define GSM     73728

__global__ void __launch_bounds__(256, 3)
gemm_mma(const bf16* __restrict__ Ah, const bf16* __restrict__ Al, int lda, long a_z,
         const bf16* __restrict__ Bh, const bf16* __restrict__ Bl, long b_z, int ldb,
         const float* __restrict__ bias, int bias_z,
         float* __restrict__ C, long c_z, int ldc,
         bf16* __restrict__ Ch, bf16* __restrict__ Cl, int ldch,
         int K, int flags)
{
    extern __shared__ char sm[];
    uint32_t sb = smem_u32(sm);
    const int tid = threadIdx.x, lane = tid & 31, wid = tid >> 5;
    const int wm = wid >> 2, wn = wid & 3;
    const int m0 = blockIdx.y * 64, n0 = blockIdx.x * 64, z = blockIdx.z;
    const bf16* Ahp = Ah + (long)z * a_z;
    const bf16* Alp = Al + (long)z * a_z;
    const bf16* Bhp = Bh + (long)z * b_z;
    const bf16* Blp = Bl + (long)z * b_z;

    const int ld_r = tid >> 3, ld_c = (tid & 7) * 8;
    const uint32_t s_wr = (uint32_t)(ld_r * TSTRIDE + ld_c * 2);

    const int a_r = (lane & 7) + ((lane >> 3) & 1) * 8;
    const int a_c8 = (lane >> 4) * 8;
    const uint32_t aoff = (uint32_t)((wm * 32 + a_r) * TSTRIDE + a_c8 * 2);
    const int b_r = (lane & 7) + (lane >> 4) * 8;
    const int b_c8 = ((lane >> 3) & 1) * 8;
    const uint32_t boff = (uint32_t)((wn * 16 + b_r) * TSTRIDE + b_c8 * 2);

    float acc[2][2][4];
#pragma unroll
    for (int i = 0; i < 2; i++)
#pragma unroll
        for (int j = 0; j < 2; j++)
#pragma unroll
            for (int q = 0; q < 4; q++) acc[i][j][q] = 0.f;

    uint32_t fah[2][2][4], fal[2][2][4], fbh[2][2][2], fbl[2][2][2];

    const int nch = K >> 6;

    auto issue = [&](int kk, int st){
        uint32_t base = sb + st * STAGE_B + s_wr;
        const bf16* ga0 = Ahp + (long)(m0 + ld_r) * lda + kk + ld_c;
        const bf16* ga1 = Alp + (long)(m0 + ld_r) * lda + kk + ld_c;
        const bf16* gb0 = Bhp + (long)(n0 + ld_r) * ldb + kk + ld_c;
        const bf16* gb1 = Blp + (long)(n0 + ld_r) * ldb + kk + ld_c;
        cpa16(base,                         ga0);
        cpa16(base + 32 * TSTRIDE,          ga0 + 32 * lda);
        cpa16(base + TILE_B,                ga1);
        cpa16(base + TILE_B + 32 * TSTRIDE, ga1 + 32 * lda);
        cpa16(base + 2 * TILE_B,                gb0);
        cpa16(base + 2 * TILE_B + 32 * TSTRIDE, gb0 + 32 * ldb);
        cpa16(base + 3 * TILE_B,                gb1);
        cpa16(base + 3 * TILE_B + 32 * TSTRIDE, gb1 + 32 * ldb);
        cpa_commit();
    };

    issue(0, 0);
    for (int i = 0; i < nch; i++) {
        if (i + 1 < nch) { issue((i + 1) << 6, (i + 1) & 1); cpa_wait<1>(); }
        else             { cpa_wait<0>(); }
        __syncthreads();

        uint32_t st = sb + (i & 1) * STAGE_B;

        {
            ldsm4(fbh[0][0][0], fbh[0][0][1], fbh[0][1][0], fbh[0][1][1], st + 2*TILE_B + boff);
            ldsm4(fbl[0][0][0], fbl[0][0][1], fbl[0][1][0], fbl[0][1][1], st + 3*TILE_B + boff);
#pragma unroll
            for (int mf = 0; mf < 2; mf++)
                ldsm4(fah[0][mf][0], fah[0][mf][1], fah[0][mf][2], fah[0][mf][3],
                      st + aoff + mf * (16*TSTRIDE));
#pragma unroll
            for (int mf = 0; mf < 2; mf++)
                ldsm4(fal[0][mf][0], fal[0][mf][1], fal[0][mf][2], fal[0][mf][3],
                      st + TILE_B + aoff + mf * (16*TSTRIDE));
        }

#pragma unroll
        for (int ks = 0; ks < 4; ks++) {
            const int cur = ks & 1, nxt = cur ^ 1;
            if (ks < 3) {
                uint32_t kb = (ks + 1) * 32;
                ldsm4(fbh[nxt][0][0], fbh[nxt][0][1], fbh[nxt][1][0], fbh[nxt][1][1],
                      st + 2*TILE_B + boff + kb);
                ldsm4(fbl[nxt][0][0], fbl[nxt][0][1], fbl[nxt][1][0], fbl[nxt][1][1],
                      st + 3*TILE_B + boff + kb);
#pragma unroll
                for (int mf = 0; mf < 2; mf++)
                    ldsm4(fah[nxt][mf][0], fah[nxt][mf][1], fah[nxt][mf][2], fah[nxt][mf][3],
                          st + aoff + mf * (16*TSTRIDE) + kb);
#pragma unroll
                for (int mf = 0; mf < 2; mf++)
                    ldsm4(fal[nxt][mf][0], fal[nxt][mf][1], fal[nxt][mf][2], fal[nxt][mf][3],
                          st + TILE_B + aoff + mf * (16*TSTRIDE) + kb);
            }
#pragma unroll
            for (int mf = 0; mf < 2; mf++)
#pragma unroll
                for (int nf = 0; nf < 2; nf++) mma16816(acc[mf][nf], fah[cur][mf], fbh[cur][nf]);
#pragma unroll
            for (int mf = 0; mf < 2; mf++)
#pragma unroll
                for (int nf = 0; nf < 2; nf++) mma16816(acc[mf][nf], fah[cur][mf], fbl[cur][nf]);
#pragma unroll
            for (int mf = 0; mf < 2; mf++)
#pragma unroll
                for (int nf = 0; nf < 2; nf++) mma16816(acc[mf][nf], fal[cur][mf], fbh[cur][nf]);
        }
        __syncthreads();
    }

    const int g = lane >> 2, tg = lane & 3;
    const float* bp = bias ? bias + (long)z * bias_z : nullptr;
    float* Cz = C ? C + (long)z * c_z : nullptr;
#pragma unroll
    for (int mf = 0; mf < 2; mf++) {
#pragma unroll
        for (int nf = 0; nf < 2; nf++) {
            int row = m0 + wm * 32 + mf * 16 + g;
            int col = n0 + wn * 16 + nf * 8 + tg * 2;
            float v0 = acc[mf][nf][0], v1 = acc[mf][nf][1];
            float v2 = acc[mf][nf][2], v3 = acc[mf][nf][3];
            if (bp) {
                float bb0 = __ldg(bp + col), bb1 = __ldg(bp + col + 1);
                v0 += bb0; v1 += bb1; v2 += bb0; v3 += bb1;
            }
            if (flags & FL_RELU) {
                v0 = fmaxf(v0, 0.f); v1 = fmaxf(v1, 0.f);
                v2 = fmaxf(v2, 0.f); v3 = fmaxf(v3, 0.f);
            }
            if (flags & FL_F32) {
                *(float2*)&Cz[(long)row * ldc + col] = make_float2(v0, v1);
                *(float2*)&Cz[(long)(row + 8) * ldc + col] = make_float2(v2, v3);
            }
            if (flags & FL_HILO) {
                bf16 h0 = __float2bfloat16(v0), h1 = __float2bfloat16(v1);
                bf16 h2 = __float2bfloat16(v2), h3 = __float2bfloat16(v3);
                __nv_bfloat162 ph0; ph0.x = h0; ph0.y = h1;
                __nv_bfloat162 ph1; ph1.x = h2; ph1.y = h3;
                __nv_bfloat162 pl0, pl1;
                pl0.x = __float2bfloat16(v0 - __bfloat162float(h0));
                pl0.y = __float2bfloat16(v1 - __bfloat162float(h1));
                pl1.x = __float2bfloat16(v2 - __bfloat162float(h2));
                pl1.y = __float2bfloat16(v3 - __bfloat162float(h3));
                *(__nv_bfloat162*)&Ch[(long)row * ldch + col] = ph0;
                *(__nv_bfloat162*)&Cl[(long)row * ldch + col] = pl0;
                *(__nv_bfloat162*)&Ch[(long)(row + 8) * ldch + col] = ph1;
                *(__nv_bfloat162*)&Cl[(long)(row + 8) * ldch + col] = pl1;
            }
        }
    }
}

// ============ small-tile bf16 variant: 32x64 CTA tile ============
#define OA_H2 0
#define OA_L2 4608
#define OB_H2 9216
#define OB_L2 18432
#define STAGE2 27648
#define GSM2 55296

__global__ void __launch_bounds__(256, 4)
gemm_sm(const bf16* __restrict__ Ah, const bf16* __restrict__ Al, int lda, long a_z,
        const bf16* __restrict__ Bh, const bf16* __restrict__ Bl, long b_z, int ldb,
        const float* __restrict__ bias, int bias_z,
        float* __restrict__ C, long c_z, int ldc,
        bf16* __restrict__ Ch, bf16* __restrict__ Cl, int ldch,
        int K, int flags)
{
    extern __shared__ char sm[];
    uint32_t sb = smem_u32(sm);
    const int tid = threadIdx.x, lane = tid & 31, wid = tid >> 5;
    const int wm = wid >> 2, wn = wid & 3;
    const int m0 = blockIdx.y * 32, n0 = blockIdx.x * 64, z = blockIdx.z;
    const bf16* Ahp = Ah + (long)z * a_z;
    const bf16* Alp = Al + (long)z * a_z;
    const bf16* Bhp = Bh + (long)z * b_z;
    const bf16* Blp = Bl + (long)z * b_z;

    const int ld_r = tid >> 3, ld_c = (tid & 7) * 8;
    const uint32_t s_wr = (uint32_t)(ld_r * TSTRIDE + ld_c * 2);

    const int a_r = (lane & 7) + ((lane >> 3) & 1) * 8;
    const int a_c8 = (lane >> 4) * 8;
    const uint32_t aoff = (uint32_t)((wm * 16 + a_r) * TSTRIDE + a_c8 * 2);
    const int b_r = (lane & 7) + (lane >> 4) * 8;
    const int b_c8 = ((lane >> 3) & 1) * 8;
    const uint32_t boff = (uint32_t)((wn * 16 + b_r) * TSTRIDE + b_c8 * 2);

    float acc[2][4];
#pragma unroll
    for (int j = 0; j < 2; j++)
#pragma unroll
        for (int q = 0; q < 4; q++) acc[j][q] = 0.f;

    uint32_t fah[2][4], fal[2][4], fbh[2][2][2], fbl[2][2][2];

    const int nch = K >> 6;

    auto issue = [&](int kk, int st){
        uint32_t base = sb + st * STAGE2 + s_wr;
        const bf16* ga0 = Ahp + (long)(m0 + ld_r) * lda + kk + ld_c;
        const bf16* ga1 = Alp + (long)(m0 + ld_r) * lda + kk + ld_c;
        const bf16* gb0 = Bhp + (long)(n0 + ld_r) * ldb + kk + ld_c;
        const bf16* gb1 = Blp + (long)(n0 + ld_r) * ldb + kk + ld_c;
        cpa16(base + OA_H2, ga0);
        cpa16(base + OA_L2, ga1);
        cpa16(base + OB_H2,                gb0);
        cpa16(base + OB_H2 + 32 * TSTRIDE, gb0 + 32 * ldb);
        cpa16(base + OB_L2,                gb1);
        cpa16(base + OB_L2 + 32 * TSTRIDE, gb1 + 32 * ldb);
        cpa_commit();
    };

    issue(0, 0);
    for (int i = 0; i < nch; i++) {
        if (i + 1 < nch) { issue((i + 1) << 6, (i + 1) & 1); cpa_wait<1>(); }
        else             { cpa_wait<0>(); }
        __syncthreads();

        uint32_t st = sb + (i & 1) * STAGE2;

        ldsm4(fbh[0][0][0], fbh[0][0][1], fbh[0][1][0], fbh[0][1][1], st + OB_H2 + boff);
        ldsm4(fbl[0][0][0], fbl[0][0][1], fbl[0][1][0], fbl[0][1][1], st + OB_L2 + boff);
        ldsm4(fah[0][0], fah[0][1], fah[0][2], fah[0][3], st + OA_H2 + aoff);
        ldsm4(fal[0][0], fal[0][1], fal[0][2], fal[0][3], st + OA_L2 + aoff);

#pragma unroll
        for (int ks = 0; ks < 4; ks++) {
            const int cur = ks & 1, nxt = cur ^ 1;
            if (ks < 3) {
                uint32_t kb = (ks + 1) * 32;
                ldsm4(fbh[nxt][0][0], fbh[nxt][0][1], fbh[nxt][1][0], fbh[nxt][1][1],
                      st + OB_H2 + boff + kb);
                ldsm4(fbl[nxt][0][0], fbl[nxt][0][1], fbl[nxt][1][0], fbl[nxt][1][1],
                      st + OB_L2 + boff + kb);
                ldsm4(fah[nxt][0], fah[nxt][1], fah[nxt][2], fah[nxt][3],
                      st + OA_H2 + aoff + kb);
                ldsm4(fal[nxt][0], fal[nxt][1], fal[nxt][2], fal[nxt][3],
                      st + OA_L2 + aoff + kb);
            }
#pragma unroll
            for (int nf = 0; nf < 2; nf++) mma16816(acc[nf], fah[cur], fbh[cur][nf]);
#pragma unroll
            for (int nf = 0; nf < 2; nf++) mma16816(acc[nf], fah[cur], fbl[cur][nf]);
#pragma unroll
            for (int nf = 0; nf < 2; nf++) mma16816(acc[nf], fal[cur], fbh[cur][nf]);
        }
        __syncthreads();
    }

    const int g = lane >> 2, tg = lane & 3;
    const float* bp = bias ? bias + (long)z * bias_z : nullptr;
    float* Cz = C ? C + (long)z * c_z : nullptr;
#pragma unroll
    for (int nf = 0; nf < 2; nf++) {
        int row = m0 + wm * 16 + g;
        int col = n0 + wn * 16 + nf * 8 + tg * 2;
        float v0 = acc[nf][0], v1 = acc[nf][1];
        float v2 = acc[nf][2], v3 = acc[nf][3];
        if (bp) {
            float bb0 = __ldg(bp + col), bb1 = __ldg(bp + col + 1);
            v0 += bb0; v1 += bb1; v2 += bb0; v3 += bb1;
        }
        if (flags & FL_RELU) {
            v0 = fmaxf(v0, 0.f); v1 = fmaxf(v1, 0.f);
            v2 = fmaxf(v2, 0.f); v3 = fmaxf(v3, 0.f);
        }
        if (flags & FL_F32) {
            *(float2*)&Cz[(long)row * ldc + col] = make_float2(v0, v1);
            *(float2*)&Cz[(long)(row + 8) * ldc + col] = make_float2(v2, v3);
        }
        if (flags & FL_HILO) {
            bf16 h0 = __float2bfloat16(v0), h1 = __float2bfloat16(v1);
            bf16 h2 = __float2bfloat16(v2), h3 = __float2bfloat16(v3);
            __nv_bfloat162 ph0; ph0.x = h0; ph0.y = h1;
            __nv_bfloat162 ph1; ph1.x = h2; ph1.y = h3;
            __nv_bfloat162 pl0, pl1;
            pl0.x = __float2bfloat16(v0 - __bfloat162float(h0));
            pl0.y = __float2bfloat16(v1 - __bfloat162float(h1));
            pl1.x = __float2bfloat16(v2 - __bfloat162float(h2));
            pl1.y = __float2bfloat16(v3 - __bfloat162float(h3));
            *(__nv_bfloat162*)&Ch[(long)row * ldch + col] = ph0;
            *(__nv_bfloat162*)&Cl[(long)row * ldch + col] = pl0;
            *(__nv_bfloat162*)&Ch[(long)(row + 8) * ldch + col] = ph1;
            *(__nv_bfloat162*)&Cl[(long)(row + 8) * ldch + col] = pl1;
        }
    }
}

// ============ fp16 SINGLE-pass GEMM, 32x64 CTA tile (continuous-path GEMMs) ============
#define HOA 0
#define HOB 4608
#define HSTAGE 13824
#define GSMH 27648

__global__ void __launch_bounds__(256, 4)
gemm_h1(const __half* __restrict__ A, const __half* __restrict__ B, long b_z,
        const float* __restrict__ bias, float* __restrict__ C, long c_z, int K)
{
    extern __shared__ char sm[];
    uint32_t sb = smem_u32(sm);
    const int tid = threadIdx.x, lane = tid & 31, wid = tid >> 5;
    const int wm = wid >> 2, wn = wid & 3;
    const int m0 = blockIdx.y * 32, n0 = blockIdx.x * 64, z = blockIdx.z;
    const __half* Bp = B + (long)z * b_z;

    const int ld_r = tid >> 3, ld_c = (tid & 7) * 8;
    const uint32_t s_wr = (uint32_t)(ld_r * TSTRIDE + ld_c * 2);

    const int a_r = (lane & 7) + ((lane >> 3) & 1) * 8;
    const int a_c8 = (lane >> 4) * 8;
    const uint32_t aoff = (uint32_t)((wm * 16 + a_r) * TSTRIDE + a_c8 * 2);
    const int b_r = (lane & 7) + (lane >> 4) * 8;
    const int b_c8 = ((lane >> 3) & 1) * 8;
    const uint32_t boff = (uint32_t)((wn * 16 + b_r) * TSTRIDE + b_c8 * 2);

    float acc[2][4];
#pragma unroll
    for (int j = 0; j < 2; j++)
#pragma unroll
        for (int q = 0; q < 4; q++) acc[j][q] = 0.f;

    uint32_t fa[2][4], fb[2][2][2];

    const int nch = K >> 6;

    auto issue = [&](int kk, int st){
        uint32_t base = sb + st * HSTAGE + s_wr;
        cpa16(base + HOA, A + (long)(m0 + ld_r) * K + kk + ld_c);
        const __half* gb = Bp + (long)(n0 + ld_r) * K + kk + ld_c;
        cpa16(base + HOB,                gb);
        cpa16(base + HOB + 32 * TSTRIDE, gb + 32 * K);
        cpa_commit();
    };

    issue(0, 0);
    for (int i = 0; i < nch; i++) {
        if (i + 1 < nch) { issue((i + 1) << 6, (i + 1) & 1); cpa_wait<1>(); }
        else             { cpa_wait<0>(); }
        __syncthreads();

        uint32_t st = sb + (i & 1) * HSTAGE;

        ldsm4(fb[0][0][0], fb[0][0][1], fb[0][1][0], fb[0][1][1], st + HOB + boff);
        ldsm4(fa[0][0], fa[0][1], fa[0][2], fa[0][3], st + HOA + aoff);

#pragma unroll
        for (int ks = 0; ks < 4; ks++) {
            const int cur = ks & 1, nxt = cur ^ 1;
            if (ks < 3) {
                uint32_t kb = (ks + 1) * 32;
                ldsm4(fb[nxt][0][0], fb[nxt][0][1], fb[nxt][1][0], fb[nxt][1][1],
                      st + HOB + boff + kb);
                ldsm4(fa[nxt][0], fa[nxt][1], fa[nxt][2], fa[nxt][3],
                      st + HOA + aoff + kb);
            }
#pragma unroll
            for (int nf = 0; nf < 2; nf++) mma16816h(acc[nf], fa[cur], fb[cur][nf]);
        }
        __syncthreads();
    }

    const int g = lane >> 2, tg = lane & 3;
    float* Cz = C + (long)z * c_z;
#pragma unroll
    for (int nf = 0; nf < 2; nf++) {
        int row = m0 + wm * 16 + g;
        int col = n0 + wn * 16 + nf * 8 + tg * 2;
        float v0 = acc[nf][0], v1 = acc[nf][1];
        float v2 = acc[nf][2], v3 = acc[nf][3];
        if (bias) {
            float bb0 = __ldg(bias + col), bb1 = __ldg(bias + col + 1);
            v0 += bb0; v1 += bb1; v2 += bb0; v3 += bb1;
        }
        *(float2*)&Cz[(long)row * DD + col] = make_float2(v0, v1);
        *(float2*)&Cz[(long)(row + 8) * DD + col] = make_float2(v2, v3);
    }
}

// ========= combined ab (bf16 3-pass, z<2) + kg (fp16 single, z>=2) =========
__global__ void __launch_bounds__(256, 4)
abkg_k(const bf16* __restrict__ nuh, const bf16* __restrict__ nul,
       const __half* __restrict__ nu16,
       const bf16* __restrict__ Wh, const bf16* __restrict__ Wl,
       const __half* __restrict__ Wkg,
       float* __restrict__ ab, float* __restrict__ trans)
{
    extern __shared__ char sm[];
    uint32_t sb = smem_u32(sm);
    const int tid = threadIdx.x, lane = tid & 31, wid = tid >> 5;
    const int wm = wid >> 2, wn = wid & 3;
    const int m0 = blockIdx.y * 32, n0 = blockIdx.x * 64, z = blockIdx.z;

    const int ld_r = tid >> 3, ld_c = (tid & 7) * 8;
    const uint32_t s_wr = (uint32_t)(ld_r * TSTRIDE + ld_c * 2);
    const int a_r = (lane & 7) + ((lane >> 3) & 1) * 8;
    const int a_c8 = (lane >> 4) * 8;
    const uint32_t aoff = (uint32_t)((wm * 16 + a_r) * TSTRIDE + a_c8 * 2);
    const int b_r = (lane & 7) + (lane >> 4) * 8;
    const int b_c8 = ((lane >> 3) & 1) * 8;
    const uint32_t boff = (uint32_t)((wn * 16 + b_r) * TSTRIDE + b_c8 * 2);
    const int g = lane >> 2, tg = lane & 3;
    const int nch = DD >> 6;

    if (z < 2) {
        const bf16* Ahp = nuh;
        const bf16* Alp = nul;
        const bf16* Bhp = Wh + (long)z * UU;
        const bf16* Blp = Wl + (long)z * UU;

        float acc[2][4];
#pragma unroll
        for (int j = 0; j < 2; j++)
#pragma unroll
            for (int q = 0; q < 4; q++) acc[j][q] = 0.f;
        uint32_t fah[2][4], fal[2][4], fbh[2][2][2], fbl[2][2][2];

        auto issue = [&](int kk, int st){
            uint32_t base = sb + st * STAGE2 + s_wr;
            const bf16* ga0 = Ahp + (long)(m0 + ld_r) * DD + kk + ld_c;
            const bf16* ga1 = Alp + (long)(m0 + ld_r) * DD + kk + ld_c;
            const bf16* gb0 = Bhp + (long)(n0 + ld_r) * DD + kk + ld_c;
            const bf16* gb1 = Blp + (long)(n0 + ld_r) * DD + kk + ld_c;
            cpa16(base + OA_H2, ga0);
            cpa16(base + OA_L2, ga1);
            cpa16(base + OB_H2,                gb0);
            cpa16(base + OB_H2 + 32 * TSTRIDE, gb0 + 32 * DD);
            cpa16(base + OB_L2,                gb1);
            cpa16(base + OB_L2 + 32 * TSTRIDE, gb1 + 32 * DD);
            cpa_commit();
        };

        issue(0, 0);
        for (int i = 0; i < nch; i++) {
            if (i + 1 < nch) { issue((i + 1) << 6, (i + 1) & 1); cpa_wait<1>(); }
            else             { cpa_wait<0>(); }
            __syncthreads();
            uint32_t st = sb + (i & 1) * STAGE2;
            ldsm4(fbh[0][0][0], fbh[0][0][1], fbh[0][1][0], fbh[0][1][1], st + OB_H2 + boff);
            ldsm4(fbl[0][0][0], fbl[0][0][1], fbl[0][1][0], fbl[0][1][1], st + OB_L2 + boff);
            ldsm4(fah[0][0], fah[0][1], fah[0][2], fah[0][3], st + OA_H2 + aoff);
            ldsm4(fal[0][0], fal[0][1], fal[0][2], fal[0][3], st + OA_L2 + aoff);
#pragma unroll
            for (int ks = 0; ks < 4; ks++) {
                const int cur = ks & 1, nxt = cur ^ 1;
                if (ks < 3) {
                    uint32_t kb = (ks + 1) * 32;
                    ldsm4(fbh[nxt][0][0], fbh[nxt][0][1], fbh[nxt][1][0], fbh[nxt][1][1],
                          st + OB_H2 + boff + kb);
                    ldsm4(fbl[nxt][0][0], fbl[nxt][0][1], fbl[nxt][1][0], fbl[nxt][1][1],
                          st + OB_L2 + boff + kb);
                    ldsm4(fah[nxt][0], fah[nxt][1], fah[nxt][2], fah[nxt][3],
                          st + OA_H2 + aoff + kb);
                    ldsm4(fal[nxt][0], fal[nxt][1], fal[nxt][2], fal[nxt][3],
                          st + OA_L2 + aoff + kb);
                }
#pragma unroll
                for (int nf = 0; nf < 2; nf++) mma16816(acc[nf], fah[cur], fbh[cur][nf]);
#pragma unroll
                for (int nf = 0; nf < 2; nf++) mma16816(acc[nf], fah[cur], fbl[cur][nf]);
#pragma unroll
                for (int nf = 0; nf < 2; nf++) mma16816(acc[nf], fal[cur], fbh[cur][nf]);
            }
            __syncthreads();
        }

        float* Cz = ab + (long)z * UU;
#pragma unroll
        for (int nf = 0; nf < 2; nf++) {
            int row = m0 + wm * 16 + g;
            int col = n0 + wn * 16 + nf * 8 + tg * 2;
            *(float2*)&Cz[(long)row * DD + col] = make_float2(acc[nf][0], acc[nf][1]);
            *(float2*)&Cz[(long)(row + 8) * DD + col] = make_float2(acc[nf][2], acc[nf][3]);
        }
    } else {
        int r = z - 1;
        const __half* Bp = Wkg + (long)r * UU;

        float acc[2][4];
#pragma unroll
        for (int j = 0; j < 2; j++)
#pragma unroll
            for (int q = 0; q < 4; q++) acc[j][q] = 0.f;
        uint32_t fa[2][4], fb[2][2][2];

        auto issue = [&](int kk, int st){
            uint32_t base = sb + st * HSTAGE + s_wr;
            cpa16(base + HOA, nu16 + (long)(m0 + ld_r) * DD + kk + ld_c);
            const __half* gb = Bp + (long)(n0 + ld_r) * DD + kk + ld_c;
            cpa16(base + HOB,                gb);
            cpa16(base + HOB + 32 * TSTRIDE, gb + 32 * DD);
            cpa_commit();
        };

        issue(0, 0);
        for (int i = 0; i < nch; i++) {
            if (i + 1 < nch) { issue((i + 1) << 6, (i + 1) & 1); cpa_wait<1>(); }
            else             { cpa_wait<0>(); }
            __syncthreads();
            uint32_t st = sb + (i & 1) * HSTAGE;
            ldsm4(fb[0][0][0], fb[0][0][1], fb[0][1][0], fb[0][1][1], st + HOB + boff);
            ldsm4(fa[0][0], fa[0][1], fa[0][2], fa[0][3], st + HOA + aoff);
#pragma unroll
            for (int ks = 0; ks < 4; ks++) {
                const int cur = ks & 1, nxt = cur ^ 1;
                if (ks < 3) {
                    uint32_t kb = (ks + 1) * 32;
                    ldsm4(fb[nxt][0][0], fb[nxt][0][1], fb[nxt][1][0], fb[nxt][1][1],
                          st + HOB + boff + kb);
                    ldsm4(fa[nxt][0], fa[nxt][1], fa[nxt][2], fa[nxt][3],
                          st + HOA + aoff + kb);
                }
#pragma unroll
                for (int nf = 0; nf < 2; nf++) mma16816h(acc[nf], fa[cur], fb[cur][nf]);
            }
            __syncthreads();
        }

        float* Cz = trans + (long)r * UU;
#pragma unroll
        for (int nf = 0; nf < 2; nf++) {
            int row = m0 + wm * 16 + g;
            int col = n0 + wn * 16 + nf * 8 + tg * 2;
            *(float2*)&Cz[(long)row * DD + col] = make_float2(acc[nf][0], acc[nf][1]);
            *(float2*)&Cz[(long)(row + 8) * DD + col] = make_float2(acc[nf][2], acc[nf][3]);
        }
    }
}

// ======================= LayerNorm 2 (residual, fp32 out) =======================
__global__ void ln2_k(const float* __restrict__ in, const float* __restrict__ add,
                      const float* __restrict__ g, const float* __restrict__ b,
                      float* __restrict__ out)
{
    int row = blockIdx.x, t = threadIdx.x;
    __shared__ float rbuf[256];
    long base = (long)row * DD;
    float v0 = in[base + t] + add[base + t];
    float v1 = in[base + t + 256] + add[base + t + 256];
    rbuf[t] = v0 + v1; __syncthreads();
    for (int s = 128; s > 0; s >>= 1) { if (t < s) rbuf[t] += rbuf[t + s]; __syncthreads(); }
    float mean = rbuf[0] * (1.0f / 512.0f);
    __syncthreads();
    float d0 = v0 - mean, d1 = v1 - mean;
    rbuf[t] = d0 * d0 + d1 * d1; __syncthreads();
    for (int s = 128; s > 0; s >>= 1) { if (t < s) rbuf[t] += rbuf[t + s]; __syncthreads(); }
    float rs = rsqrtf(rbuf[0] * (1.0f / 512.0f) + 1e-5f);
    out[base + t]       = d0 * rs * g[t]       + b[t];
    out[base + t + 256] = d1 * rs * g[t + 256] + b[t + 256];
}

// ========== fused attention: scores + softmax + ctx, 16-row tiles ==========
__global__ void attn_fused_k(const float* __restrict__ q, const float* __restrict__ k,
                             const float* __restrict__ v, float* __restrict__ attn,
                             bf16* __restrict__ ch, bf16* __restrict__ cl)
{
    int it = blockIdx.x, h = blockIdx.y, b = blockIdx.z;  // 256 thr
    int t = threadIdx.x;
    int i0 = it * 16;
    __shared__ float ks[SS][DH + 1];
    __shared__ float qs[16][DH + 1];
    __shared__ float P[16][SS];
    const float* kbase = k + (long)b * SS * DD + h * DH;
    const float* qbase = q + (long)b * SS * DD + h * DH;
    for (int idx = t; idx < SS * DH; idx += 256) {
        int j = idx >> 6, d = idx & 63;
        ks[j][d] = kbase[(long)j * DD + d];
    }
    for (int idx = t; idx < 16 * DH; idx += 256) {
        int r = idx >> 6, d = idx & 63;
        qs[r][d] = qbase[(long)(i0 + r) * DD + d];
    }
    __syncthreads();
    {
        int j = t & 127, grp = t >> 7;
#pragma unroll
        for (int r = 0; r < 8; r++) {
            int i = grp * 8 + r;
            float acc = 0.f;
#pragma unroll
            for (int d = 0; d < DH; d++) acc += qs[i][d] * ks[j][d];
            P[i][j] = acc * 0.125f;
        }
    }
    __syncthreads();
    {
        int w = t >> 5, ln = t & 31;
        long obase = (((long)(b * HH + h) * SS) + i0) * SS;
#pragma unroll
        for (int rr = 0; rr < 2; rr++) {
            int i = w * 2 + rr;
            float m = -1e30f;
#pragma unroll
            for (int c = 0; c < 4; c++) m = fmaxf(m, P[i][ln + c * 32]);
#pragma unroll
            for (int o = 16; o > 0; o >>= 1) m = fmaxf(m, __shfl_xor_sync(0xffffffffu, m, o));
            float s = 0.f, e[4];
#pragma unroll
            for (int c = 0; c < 4; c++) { e[c] = expf(P[i][ln + c * 32] - m); s += e[c]; }
#pragma unroll
            for (int o = 16; o > 0; o >>= 1) s += __shfl_xor_sync(0xffffffffu, s, o);
            float inv = 1.0f / s;
#pragma unroll
            for (int c = 0; c < 4; c++) {
                float pv = e[c] * inv;
                P[i][ln + c * 32] = pv;
                attn[obase + (long)i * SS + ln + c * 32] = pv;
            }
        }
    }
    __syncthreads();
    const float* vbase = v + (long)b * SS * DD + h * DH;
    for (int idx = t; idx < SS * DH; idx += 256) {
        int j = idx >> 6, dd = idx & 63;
        ks[j][dd] = vbase[(long)j * DD + dd];
    }
    __syncthreads();
    {
        int d = t & 63, ig = t >> 6;
        float acc[4] = {0.f, 0.f, 0.f, 0.f};
#pragma unroll
        for (int jh = 0; jh < 2; jh++) {
            float vreg[64];
#pragma unroll
            for (int jj = 0; jj < 64; jj++) vreg[jj] = ks[jh * 64 + jj][d];
#pragma unroll
            for (int r = 0; r < 4; r++) {
                int i = ig + 4 * r;
                float a = acc[r];
#pragma unroll
                for (int jj = 0; jj < 64; jj++) a += P[i][jh * 64 + jj] * vreg[jj];
                acc[r] = a;
            }
        }
#pragma unroll
        for (int r = 0; r < 4; r++) {
            int i = ig + 4 * r;
            long o = (long)(b * SS + i0 + i) * DD + h * DH + d;
            bf16 hh = __float2bfloat16(acc[r]);
            ch[o] = hh; cl[o] = __float2bfloat16(acc[r] - __bfloat162float(hh));
        }
    }
}

// ======== pair classifier on compacted edges: one warp per edge ========
__global__ void __launch_bounds__(256)
pair2_k(const float* __restrict__ ap, const float* __restrict__ bp,
        const float* __restrict__ rc_b1, const float* __restrict__ rc_w2,
        const float* __restrict__ rc_b2,
        const int2* __restrict__ elist, const int* __restrict__ ecnt,
        int* __restrict__ rel)
{
    int total = *ecnt; if (total > MAXE) total = MAXE;
    int wg = blockIdx.x * 8 + (threadIdx.x >> 5);
    int nw = gridDim.x * 8;
    int lane = threadIdx.x & 31;

    for (int e = wg; e < total; e += nw) {
        int2 ed = elist[e];
        int bu = ed.x, v = ed.y;
        int bb = bu >> 7;
        const float* A = ap + (long)bu * DD;
        const float* B = bp + ((long)(bb * SS + v)) * DD;
        float acc[RR];
#pragma unroll
        for (int r = 0; r < RR; r++) acc[r] = 0.f;
#pragma unroll
        for (int c = 0; c < 4; c++) {
            int d = c * 128 + lane * 4;
            float4 a4 = *(const float4*)(A + d);
            float4 b4 = *(const float4*)(B + d);
            float4 c4 = *(const float4*)(rc_b1 + d);
            float hs[4];
            hs[0] = fmaxf(a4.x + b4.x + c4.x, 0.f);
            hs[1] = fmaxf(a4.y + b4.y + c4.y, 0.f);
            hs[2] = fmaxf(a4.z + b4.z + c4.z, 0.f);
            hs[3] = fmaxf(a4.w + b4.w + c4.w, 0.f);
#pragma unroll
            for (int j = 0; j < 4; j++) {
                float4 w0 = *(const float4*)(rc_w2 + (long)(d + j) * RR);
                float4 w1 = *(const float4*)(rc_w2 + (long)(d + j) * RR + 4);
                acc[0] += hs[j] * w0.x; acc[1] += hs[j] * w0.y;
                acc[2] += hs[j] * w0.z; acc[3] += hs[j] * w0.w;
                acc[4] += hs[j] * w1.x; acc[5] += hs[j] * w1.y;
                acc[6] += hs[j] * w1.z; acc[7] += hs[j] * w1.w;
            }
        }
#pragma unroll
        for (int r = 0; r < RR; r++)
#pragma unroll
            for (int o = 16; o > 0; o >>= 1)
                acc[r] += __shfl_xor_sync(0xffffffffu, acc[r], o);
        if (lane == 0) {
            int pred = 0; float best = acc[0] + rc_b2[0];
#pragma unroll
            for (int r = 1; r < RR; r++) {
                float lg = acc[r] + rc_b2[r];
                if (lg > best) { best = lg; pred = r; }
            }
            if (pred != 0) rel[(long)bu * SS + v] = pred;
        }
    }
}

// ==== nu: reduce split-K partials + bias + bf16 hi/lo + fp16, PLUS fused edge extraction ====
__global__ void conv_nu_k(const float* __restrict__ P, const float* __restrict__ b2,
                          const float* __restrict__ attn,
                          float* __restrict__ nu, bf16* __restrict__ H, bf16* __restrict__ L,
                          __half* __restrict__ N16,
                          int* __restrict__ rel, int2* __restrict__ elist,
                          int* __restrict__ ecnt)
{
    int row = blockIdx.x, t = threadIdx.x;  // 256; row == bu
    // fused edges: threads 0..127 handle v = t for this bu (identical math to old edges_k)
    if (t < SS) {
        int b = row >> 7, u = row & 127, v = t;
        float s = 0.f;
#pragma unroll
        for (int h = 0; h < HH; h++)
            s += attn[(((long)(b * HH + h) * SS) + u) * SS + v];
        s *= 0.125f;
        long ridx = (long)row * SS + v;
        rel[ridx] = 0;
        if ((s > THRESH) && (u != v)) {
            int p = atomicAdd(ecnt, 1);
            if (p < MAXE) elist[p] = make_int2(row, v);
        }
    }
    for (int c = t; c < DD; c += 256) {
        long i = (long)row * DD + c;
        float v = b2[c] + P[i] + P[UU + i] + P[2L*UU + i] + P[3L*UU + i];
        nu[i] = v;
        bf16 h = __float2bfloat16(v);
        H[i] = h; L[i] = __float2bfloat16(v - __bfloat162float(h));
        N16[i] = __float2half(v);
    }
}

// ======================= edge aggregation (writes reasoned fp16) =======================
__global__ void agg_k(const int* __restrict__ rel, const float* __restrict__ trans,
                      const float* __restrict__ nu, __half* __restrict__ r16)
{
    int bv = blockIdx.x;                 // b*S + v
    int b = bv >> 7, v = bv & 127, t = threadIdx.x;   // 256
    __shared__ int sr[SS];
    if (t < SS) sr[t] = rel[((long)b * SS + t) * SS + v];
    __syncthreads();
    float a0 = 0.f, a1 = 0.f;
    for (int u = 0; u < SS; u++) {
        int r = sr[u];
        if (r) {
            const float* tr = trans + (long)r * UU + (long)(b * SS + u) * DD;
            a0 += tr[t]; a1 += tr[t + 256];
        }
    }
    long row = (long)bv * DD;
    r16[row + t]       = __float2half(nu[row + t] + a0);
    r16[row + t + 256] = __float2half(nu[row + t + 256] + a1);
}

// ======================= launch =======================
extern "C" void kernel_launch(void* const* d_in, const int* in_sizes, int n_in,
                              void* d_out, int out_size)
{
    const float* x     = (const float*)d_in[0];
    const float* ln1_g = (const float*)d_in[1];
    const float* ln1_b = (const float*)d_in[2];
    const float* wq    = (const float*)d_in[3];
    const float* bq    = (const float*)d_in[4];
    const float* wk    = (const float*)d_in[5];
    const float* bk    = (const float*)d_in[6];
    const float* wv    = (const float*)d_in[7];
    const float* bvv   = (const float*)d_in[8];
    const float* wo    = (const float*)d_in[9];
    const float* bo    = (const float*)d_in[10];
    const float* w1    = (const float*)d_in[11];
    const float* b1    = (const float*)d_in[12];
    const float* w2    = (const float*)d_in[13];
    const float* b2    = (const float*)d_in[14];
    const float* rc_w1 = (const float*)d_in[15];
    const float* rc_b1 = (const float*)d_in[16];
    const float* rc_w2 = (const float*)d_in[17];
    const float* rc_b2 = (const float*)d_in[18];
    const float* kg_w  = (const float*)d_in[19];
    const float* s2n_w = (const float*)d_in[20];
    const float* s2n_b = (const float*)d_in[21];
    const float* ln2_g = (const float*)d_in[22];
    const float* ln2_b = (const float*)d_in[23];
    float* out = (float*)d_out;

    bf16 *wTh, *wTl, *xnh, *xnl, *ctxh, *ctxl, *aoh, *aol, *hidh, *hidl, *nuh, *nul;
    __half *wT16, *nu16, *rs16;
    float *b3, *qkv, *attn, *nupart, *nu, *ab, *trans, *nr;
    int *rel, *ecnt;
    int2 *elist;
    cudaGetSymbolAddress((void**)&wTh, g_wTh);   cudaGetSymbolAddress((void**)&wTl, g_wTl);
    cudaGetSymbolAddress((void**)&wT16, g_wT16);
    cudaGetSymbolAddress((void**)&b3, g_b3);
    cudaGetSymbolAddress((void**)&xnh, g_xnh);   cudaGetSymbolAddress((void**)&xnl, g_xnl);
    cudaGetSymbolAddress((void**)&qkv, g_qkv);
    cudaGetSymbolAddress((void**)&attn, g_attn);
    cudaGetSymbolAddress((void**)&ctxh, g_ctxh); cudaGetSymbolAddress((void**)&ctxl, g_ctxl);
    cudaGetSymbolAddress((void**)&aoh, g_aoh);   cudaGetSymbolAddress((void**)&aol, g_aol);
    cudaGetSymbolAddress((void**)&hidh, g_hidh); cudaGetSymbolAddress((void**)&hidl, g_hidl);
    cudaGetSymbolAddress((void**)&nupart, g_nupart);
    cudaGetSymbolAddress((void**)&nu, g_nu);
    cudaGetSymbolAddress((void**)&nuh, g_nuh);   cudaGetSymbolAddress((void**)&nul, g_nul);
    cudaGetSymbolAddress((void**)&nu16, g_nu16);
    cudaGetSymbolAddress((void**)&ab, g_ab);
    cudaGetSymbolAddress((void**)&trans, g_trans);
    cudaGetSymbolAddress((void**)&rel, g_rel);
    cudaGetSymbolAddress((void**)&rs16, g_rs16);
    cudaGetSymbolAddress((void**)&nr, g_nr);
    cudaGetSymbolAddress((void**)&elist, g_elist);
    cudaGetSymbolAddress((void**)&ecnt, g_ecnt);

    cudaFuncSetAttribute(gemm_mma, cudaFuncAttributeMaxDynamicSharedMemorySize, GSM);
    cudaFuncSetAttribute(gemm_mma, cudaFuncAttributePreferredSharedMemoryCarveout, 100);
    cudaFuncSetAttribute(gemm_sm, cudaFuncAttributeMaxDynamicSharedMemorySize, GSM2);
    cudaFuncSetAttribute(gemm_sm, cudaFuncAttributePreferredSharedMemoryCarveout, 100);
    cudaFuncSetAttribute(gemm_h1, cudaFuncAttributeMaxDynamicSharedMemorySize, GSMH);
    cudaFuncSetAttribute(gemm_h1, cudaFuncAttributePreferredSharedMemoryCarveout, 100);
    cudaFuncSetAttribute(abkg_k, cudaFuncAttributeMaxDynamicSharedMemorySize, GSM2);
    cudaFuncSetAttribute(abkg_k, cudaFuncAttributePreferredSharedMemoryCarveout, 100);

    // fused prep: weight transpose/convert + ln1 + bias pack + edge-counter reset
    prep_k<<<WBLK + BS, 256>>>(wq, wk, wv, wo, w1, w2, rc_w1, kg_w, s2n_w,
                               bq, bk, bvv, x, ln1_g, ln1_b, xnh, xnl);

    // QKV (z=3), fp32 out — small tile for 384 CTAs
    gemm_sm<<<dim3(8, 16, 3), 256, GSM2>>>(xnh, xnl, DD, 0, wTh, wTl, UU, DD,
                                           b3, DD, qkv, UU, DD, nullptr, nullptr, 0,
                                           DD, FL_F32);
    // fused attention (scores + softmax + ctx)
    attn_fused_k<<<dim3(8, HH, BB), 256>>>(qkv, qkv + UU, qkv + 2 * UU, attn, ctxh, ctxl);

    // ao = ctx @ wo + bo  (hi/lo only) — small tile
    gemm_sm<<<dim3(8, 16, 1), 256, GSM2>>>(ctxh, ctxl, DD, 0, wTh + 3L*UU, wTl + 3L*UU, 0, DD,
                                           bo, 0, nullptr, 0, 0, aoh, aol, DD,
                                           DD, FL_HILO);
    // hid = relu(ao @ w1 + b1) (hi/lo only, N=2048) — big tile
    gemm_mma<<<dim3(32, 8, 1), 256, GSM>>>(aoh, aol, DD, 0, wTh + 4L*UU, wTl + 4L*UU, 0, DD,
                                           b1, 0, nullptr, 0, 0, hidh, hidl, FF,
                                           DD, FL_HILO | FL_RELU);
    // nu partials = hid @ w2  (split-K z=4 into 4 slabs)
    gemm_mma<<<dim3(8, 8, 4), 256, GSM>>>(hidh, hidl, FF, DD, wTh + 8L*UU, wTl + 8L*UU, DD, FF,
                                          nullptr, 0, nupart, UU, DD, nullptr, nullptr, 0,
                                          DD, FL_F32);
    // conv_nu + fused edge extraction (edges input attn ready since attention)
    conv_nu_k<<<BS, 256>>>(nupart, b2, attn, nu, nuh, nul, nu16, rel, elist, ecnt);

    // ab (bf16 3-pass, z<2) + kg (fp16 single, z=2..8) in ONE launch
    abkg_k<<<dim3(8, 16, 9), 256, GSM2>>>(nuh, nul, nu16,
                                          wTh + 12L*UU, wTl + 12L*UU, wT16, ab, trans);

    // relation classifier on compacted edges only
    pair2_k<<<64, 256>>>(ab, ab + UU, rc_b1, rc_w2, rc_b2, elist, ecnt, rel);

    // aggregation -> reasoned fp16
    agg_k<<<BS, 256>>>(rel, trans, nu, rs16);

    // s2n projection, fp16 single pass (continuous path)
    gemm_h1<<<dim3(8, 16, 1), 256, GSMH>>>(rs16, wT16 + 8L*UU, 0,
                                           s2n_b, nr, 0, DD);
    // final residual LN
    ln2_k<<<BS, 256>>>(nr, x, ln2_g, ln2_b, out);
}